// round 8
// baseline (speedup 1.0000x reference)
#include <cuda_runtime.h>
#include <cstdint>

typedef unsigned long long ull;

#define KKn  9
#define Bn   8
#define Cn   256
#define Hn   96
#define Wn   96
#define On   256
#define HWn  (Hn*Wn)          // 9216
#define KDIM (Cn*KKn)         // 2304

// ---- main kernel: warp-specialized ----
#define NT   192              // 128 consumers + 64 producers
#define NC   128
#define NP   64
#define TP   16               // pixels per block
#define SSTR 260              // s row stride (floats)
#define BK   32               // k-chunk per w stage
#define NCHUNK (KDIM/BK)      // 72
#define CPK   8               // chunks per kk slice (256/BK)
#define WSTR 36               // w smem row stride (floats)
#define WBUF (On*WSTR)        // 9216 floats
#define SBUF (TP*SSTR)        // 4160 floats

#define SMEM_FLOATS (2*SBUF + 2*WBUF + 3*TP*KKn)
#define SMEM_BYTES  (SMEM_FLOATS*4)   // 108,736 B -> 2 blocks/SM

// named barrier ids (full: P membar+arrive / C sync;  empty: C arrive / P sync)
#define BAR_FW(bb) (1+(bb))
#define BAR_EW(bb) (3+(bb))
#define BAR_FS(bb) (5+(bb))
#define BAR_ES(bb) (7+(bb))
#define BAR_PROD   9

// ---------------- scratch ----------------
__device__ float g_xt[Bn*HWn*Cn];        // x transposed to NHWC
__device__ float g_py [Bn*KKn*HWn];
__device__ float g_px [Bn*KKn*HWn];
__device__ float g_msk[Bn*KKn*HWn];
__device__ float g_wsoff[Cn*KKn*28];
__device__ float g_wt2[On*KDIM];         // [o][kk*256+c]
__device__ float g_bnA[On];
__device__ float g_bnB[On];

// ---------------- helpers ----------------
__device__ __forceinline__ ull pk2(float a, float b) {
    ull r; asm("mov.b64 %0, {%1, %2};" : "=l"(r) : "f"(a), "f"(b)); return r;
}
__device__ __forceinline__ void unpk(ull v, float& a, float& b) {
    asm("mov.b64 {%0, %1}, %2;" : "=f"(a), "=f"(b) : "l"(v));
}
__device__ __forceinline__ void fma2(ull& d, ull a, ull b) {
    asm("fma.rn.f32x2 %0, %1, %2, %0;" : "+l"(d) : "l"(a), "l"(b));
}
__device__ __forceinline__ uint32_t smem_u32(const void* p) {
    return (uint32_t)__cvta_generic_to_shared(p);
}
__device__ __forceinline__ void cp16(uint32_t dst, const void* src) {
    asm volatile("cp.async.cg.shared.global [%0], [%1], 16;" :: "r"(dst), "l"(src));
}
#define CP_COMMIT()  asm volatile("cp.async.commit_group;")
#define CP_WAIT0()   asm volatile("cp.async.wait_group 0;")
__device__ __forceinline__ void bar_sync(int id, int cnt) {
    asm volatile("bar.sync %0, %1;" :: "r"(id), "r"(cnt) : "memory");
}
__device__ __forceinline__ void bar_arrive(int id, int cnt) {
    asm volatile("bar.arrive %0, %1;" :: "r"(id), "r"(cnt) : "memory");
}
__device__ __forceinline__ void membar_cta() {
    asm volatile("membar.cta;" ::: "memory");
}

// ---------------- prep ----------------
__global__ void prep_kernel(const float* __restrict__ w_off,
                            const float* __restrict__ w_dcn,
                            const float* __restrict__ b_dcn,
                            const float* __restrict__ gamma,
                            const float* __restrict__ beta,
                            const float* __restrict__ rmean,
                            const float* __restrict__ rvar) {
    int t = blockIdx.x * blockDim.x + threadIdx.x;
    int stride = gridDim.x * blockDim.x;
    for (int i = t; i < Cn*KKn*28; i += stride) {
        int oc = i % 28; int rest = i / 28;
        int kk = rest % KKn; int c = rest / KKn;
        g_wsoff[i] = (oc < 27) ? w_off[(oc*Cn + c)*KKn + kk] : 0.f;
    }
    for (int i = t; i < On*KDIM; i += stride) {
        int K = i % KDIM; int o = i / KDIM;
        int kk = K / Cn;  int c = K % Cn;
        g_wt2[i] = w_dcn[(o*Cn + c)*KKn + kk];
    }
    if (t < On) {
        float inv = rsqrtf(rvar[t] + 1e-5f);
        float A = gamma[t] * inv;
        g_bnA[t] = A;
        g_bnB[t] = (b_dcn[t] - rmean[t]) * A + beta[t];
    }
}

// ---------------- NCHW -> NHWC transpose ----------------
__global__ void transpose_kernel(const float* __restrict__ x) {
    __shared__ float tile[32][33];
    int bh = blockIdx.z;
    int c0 = blockIdx.y * 32;
    int w0 = blockIdx.x * 32;
    int b = bh / Hn; int h = bh % Hn;
    for (int i = threadIdx.y; i < 32; i += 8)
        tile[i][threadIdx.x] = x[((b*Cn + c0 + i)*Hn + h)*Wn + w0 + threadIdx.x];
    __syncthreads();
    for (int i = threadIdx.y; i < 32; i += 8)
        g_xt[((size_t)(b*Hn + h)*Wn + w0 + i)*Cn + c0 + threadIdx.x] = tile[threadIdx.x][i];
}

// ---------------- offset conv ----------------
__global__ __launch_bounds__(128) void offset_kernel(const float* __restrict__ x,
                                                     const float* __restrict__ b_off) {
    __shared__ float ws[32*KKn*28];
    int pix = blockIdx.x * 128 + threadIdx.x;
    int b = pix / HWn; int hw = pix % HWn;
    int h = hw / Wn;   int w = hw % Wn;

    ull acc[14];
    #pragma unroll
    for (int q = 0; q < 14; q++) acc[q] = 0ull;

    for (int c0 = 0; c0 < Cn; c0 += 32) {
        __syncthreads();
        for (int i = threadIdx.x; i < 32*KKn*28; i += 128)
            ws[i] = g_wsoff[c0*KKn*28 + i];
        __syncthreads();
        for (int c = 0; c < 32; c++) {
            const float* xr = x + ((size_t)(b*Cn + c0 + c)*Hn)*Wn;
            #pragma unroll
            for (int kk = 0; kk < 9; kk++) {
                int dy = kk/3 - 1, dx = kk%3 - 1;
                int yy = h + dy, xx = w + dx;
                float xv = 0.f;
                if ((unsigned)yy < (unsigned)Hn && (unsigned)xx < (unsigned)Wn)
                    xv = xr[yy*Wn + xx];
                ull xv2 = pk2(xv, xv);
                const ulonglong2* wrow = (const ulonglong2*)(ws + (c*KKn + kk)*28);
                #pragma unroll
                for (int q = 0; q < 7; q++) {
                    ulonglong2 wv = wrow[q];
                    fma2(acc[2*q],   wv.x, xv2);
                    fma2(acc[2*q+1], wv.y, xv2);
                }
            }
        }
    }

    float v[28];
    #pragma unroll
    for (int q = 0; q < 14; q++) unpk(acc[q], v[2*q], v[2*q+1]);

    #pragma unroll
    for (int k = 0; k < 9; k++) {
        int dy = k/3 - 1, dx = k%3 - 1;
        float py = v[2*k]   + b_off[2*k]   + (float)(h + dy);
        float px = v[2*k+1] + b_off[2*k+1] + (float)(w + dx);
        float mv = v[18+k] + b_off[18+k];
        float mm = 1.f / (1.f + expf(-mv));
        int idx = (b*KKn + k)*HWn + hw;
        g_py[idx] = py; g_px[idx] = px; g_msk[idx] = mm;
    }
}

// ---------------- main: warp-specialized fused DCN ----------------
__device__ __forceinline__ float4 corner_ld(const float* __restrict__ xtb, int y, int x, int c4) {
    if ((unsigned)y < (unsigned)Hn && (unsigned)x < (unsigned)Wn)
        return *(const float4*)(xtb + ((y*Wn + x) << 8) + (c4 << 2));
    return make_float4(0.f, 0.f, 0.f, 0.f);
}

// producer gather of one kk slice: thread tp owns c4 column = tp, all TP pixels.
__device__ __forceinline__ void gather_slice(
    const float* __restrict__ xtb, float* __restrict__ sd,
    const float* __restrict__ spy, const float* __restrict__ spx,
    const float* __restrict__ smk, int kk, int tp)
{
    #pragma unroll 1
    for (int pp = 0; pp < TP; pp += 2) {
        float4 A0[4], A1[4];
        float wy0, wx0, mm0, wy1, wx1, mm1;
        {
            float py = spy[pp*KKn + kk], px = spx[pp*KKn + kk];
            mm0 = smk[pp*KKn + kk];
            float fy = floorf(py), fx = floorf(px);
            int y0 = (int)fy, x0 = (int)fx;
            wy0 = py - fy; wx0 = px - fx;
            A0[0] = corner_ld(xtb, y0,   x0,   tp);
            A0[1] = corner_ld(xtb, y0,   x0+1, tp);
            A0[2] = corner_ld(xtb, y0+1, x0,   tp);
            A0[3] = corner_ld(xtb, y0+1, x0+1, tp);
        }
        {
            float py = spy[(pp+1)*KKn + kk], px = spx[(pp+1)*KKn + kk];
            mm1 = smk[(pp+1)*KKn + kk];
            float fy = floorf(py), fx = floorf(px);
            int y0 = (int)fy, x0 = (int)fx;
            wy1 = py - fy; wx1 = px - fx;
            A1[0] = corner_ld(xtb, y0,   x0,   tp);
            A1[1] = corner_ld(xtb, y0,   x0+1, tp);
            A1[2] = corner_ld(xtb, y0+1, x0,   tp);
            A1[3] = corner_ld(xtb, y0+1, x0+1, tp);
        }
        {
            float w00 = (1.f-wy0)*(1.f-wx0), w01 = (1.f-wy0)*wx0;
            float w10 = wy0*(1.f-wx0),       w11 = wy0*wx0;
            float4 r;
            r.x = (A0[0].x*w00 + A0[1].x*w01 + A0[2].x*w10 + A0[3].x*w11) * mm0;
            r.y = (A0[0].y*w00 + A0[1].y*w01 + A0[2].y*w10 + A0[3].y*w11) * mm0;
            r.z = (A0[0].z*w00 + A0[1].z*w01 + A0[2].z*w10 + A0[3].z*w11) * mm0;
            r.w = (A0[0].w*w00 + A0[1].w*w01 + A0[2].w*w10 + A0[3].w*w11) * mm0;
            *(float4*)(sd + pp*SSTR + tp*4) = r;
        }
        {
            float w00 = (1.f-wy1)*(1.f-wx1), w01 = (1.f-wy1)*wx1;
            float w10 = wy1*(1.f-wx1),       w11 = wy1*wx1;
            float4 r;
            r.x = (A1[0].x*w00 + A1[1].x*w01 + A1[2].x*w10 + A1[3].x*w11) * mm1;
            r.y = (A1[0].y*w00 + A1[1].y*w01 + A1[2].y*w10 + A1[3].y*w11) * mm1;
            r.z = (A1[0].z*w00 + A1[1].z*w01 + A1[2].z*w10 + A1[3].z*w11) * mm1;
            r.w = (A1[0].w*w00 + A1[1].w*w01 + A1[2].w*w10 + A1[3].w*w11) * mm1;
            *(float4*)(sd + (pp+1)*SSTR + tp*4) = r;
        }
    }
}

__global__ __launch_bounds__(NT, 2) void main_kernel(float* __restrict__ out) {
    extern __shared__ float smem[];
    float* s0  = smem;
    float* s1  = smem + SBUF;
    float* wb0 = smem + 2*SBUF;
    float* wb1 = wb0 + WBUF;
    float* spy = wb1 + WBUF;
    float* spx = spy + TP*KKn;
    float* smk = spx + TP*KKn;

    int tid  = threadIdx.x;
    int pixb = blockIdx.x * TP;
    int b    = pixb / HWn;
    int hwb  = pixb % HWn;

    if (tid < NC) {
        // ================= CONSUMER (warps 0-3): pure LDS + FFMA2 =================
        int og = tid >> 2;        // 0..31 -> o = og + 32*j
        int pg = tid & 3;         // 0..3  -> p = pg + 4*i

        ull acc[8][4];
        #pragma unroll
        for (int j = 0; j < 8; j++)
            #pragma unroll
            for (int i = 0; i < 4; i++) acc[j][i] = 0ull;

        int q = 0;
        #pragma unroll 1
        for (int kk = 0; kk < KKn; kk++) {
            int ssel = kk & 1;
            bar_sync(BAR_FS(ssel), NT);
            const float* sp = (ssel ? s1 : s0) + pg*SSTR;

            #pragma unroll 1
            for (int cc = 0; cc < CPK; cc++) {
                int wsel = q & 1;
                bar_sync(BAR_FW(wsel), NT);
                const float* wbp = wsel ? wb1 : wb0;
                const float* spc = sp + cc*BK;

                #pragma unroll
                for (int kq = 0; kq < BK/4; kq++) {
                    ulonglong2 sv0 = *(const ulonglong2*)(spc + 0*4*SSTR + kq*4);
                    ulonglong2 sv1 = *(const ulonglong2*)(spc + 1*4*SSTR + kq*4);
                    ulonglong2 sv2 = *(const ulonglong2*)(spc + 2*4*SSTR + kq*4);
                    ulonglong2 sv3 = *(const ulonglong2*)(spc + 3*4*SSTR + kq*4);
                    #pragma unroll
                    for (int j = 0; j < 8; j++) {
                        ulonglong2 wv = *(const ulonglong2*)(wbp + (og + 32*j)*WSTR + kq*4);
                        fma2(acc[j][0], wv.x, sv0.x);
                        fma2(acc[j][0], wv.y, sv0.y);
                        fma2(acc[j][1], wv.x, sv1.x);
                        fma2(acc[j][1], wv.y, sv1.y);
                        fma2(acc[j][2], wv.x, sv2.x);
                        fma2(acc[j][2], wv.y, sv2.y);
                        fma2(acc[j][3], wv.x, sv3.x);
                        fma2(acc[j][3], wv.y, sv3.y);
                    }
                }
                bar_arrive(BAR_EW(wsel), NT);
                q++;
            }
            bar_arrive(BAR_ES(ssel), NT);
        }

        // ---- epilogue: BN + ReLU ----
        #pragma unroll
        for (int j = 0; j < 8; j++) {
            int o = og + 32*j;
            float A = g_bnA[o], Bb = g_bnB[o];
            float* orow = out + (size_t)(b*On + o)*HWn + hwb;
            #pragma unroll
            for (int i = 0; i < 4; i++) {
                float lo, hi; unpk(acc[j][i], lo, hi);
                float r = (lo + hi) * A + Bb;
                orow[pg + 4*i] = fmaxf(r, 0.f);
            }
        }
    } else {
        // ================= PRODUCER (warps 4-5): gather + cp.async =================
        int tp = tid - NC;   // 0..63

        // coords
        for (int i = tp; i < TP*KKn; i += NP) {
            int p = i / KKn, k = i % KKn;
            int gi = (b*KKn + k)*HWn + hwb + p;
            spy[i] = g_py[gi]; spx[i] = g_px[gi]; smk[i] = g_msk[gi];
        }
        bar_sync(BAR_PROD, NP);

        const float* xtb = g_xt + (size_t)b * (HWn*Cn);

        // prime slice 0
        gather_slice(xtb, s0, spy, spx, smk, 0, tp);
        membar_cta();
        bar_arrive(BAR_FS(0), NT);

        int q = 0;
        #pragma unroll 1
        for (int kk = 0; kk < KKn; kk++) {
            #pragma unroll 1
            for (int cc = 0; cc < CPK; cc++) {
                int wsel = q & 1;
                if (q >= 2) bar_sync(BAR_EW(wsel), NT);

                // cp chunk q: 2048 cp16 over 64 threads, coalesced
                const float* gs = g_wt2 + q*BK;
                uint32_t dstb = smem_u32(wsel ? wb1 : wb0);
                #pragma unroll
                for (int j = 0; j < 32; j++) {
                    int g = j*NP + tp;
                    int row = g >> 3;
                    int quad = g & 7;
                    cp16(dstb + (uint32_t)(row*WSTR + quad*4)*4,
                         gs + (size_t)row*KDIM + quad*4);
                }
                CP_COMMIT();
                CP_WAIT0();
                membar_cta();
                bar_arrive(BAR_FW(wsel), NT);

                // after chunk 1 of this slice: gather next slice
                if (cc == 1 && kk + 1 < KKn) {
                    int nb = (kk + 1) & 1;
                    if (kk + 1 >= 2) bar_sync(BAR_ES(nb), NT);
                    gather_slice(xtb, nb ? s1 : s0, spy, spx, smk, kk + 1, tp);
                    membar_cta();
                    bar_arrive(BAR_FS(nb), NT);
                }
                q++;
            }
        }
    }
}

// ---------------- launch ----------------
extern "C" void kernel_launch(void* const* d_in, const int* in_sizes, int n_in,
                              void* d_out, int out_size) {
    const float* x      = (const float*)d_in[0];
    const float* w_off  = (const float*)d_in[1];
    const float* b_off  = (const float*)d_in[2];
    const float* w_dcn  = (const float*)d_in[3];
    const float* b_dcn  = (const float*)d_in[4];
    const float* gamma  = (const float*)d_in[5];
    const float* beta   = (const float*)d_in[6];
    const float* rmean  = (const float*)d_in[7];
    const float* rvar   = (const float*)d_in[8];
    float* out = (float*)d_out;

    cudaFuncSetAttribute(main_kernel, cudaFuncAttributeMaxDynamicSharedMemorySize, SMEM_BYTES);
    cudaFuncSetAttribute(main_kernel, cudaFuncAttributePreferredSharedMemoryCarveout, 100);

    prep_kernel<<<256, 256>>>(w_off, w_dcn, b_dcn, gamma, beta, rmean, rvar);

    dim3 tgrid(Wn/32, Cn/32, Bn*Hn);
    transpose_kernel<<<tgrid, dim3(32, 8)>>>(x);

    offset_kernel<<<(Bn*HWn)/128, 128>>>(x, b_off);

    main_kernel<<<(Bn*HWn)/TP, NT, SMEM_BYTES>>>(out);
}

// round 10
// speedup vs baseline: 1.9090x; 1.9090x over previous
#include <cuda_runtime.h>
#include <cuda_bf16.h>
#include <cstdint>

typedef unsigned long long ull;

#define KKn  9
#define Bn   8
#define Cn   256
#define Hn   96
#define Wn   96
#define On   256
#define HWn  (Hn*Wn)          // 9216
#define KDIM (Cn*KKn)         // 2304

// ---- main mma kernel ----
#define NT    256
#define TPIX  64              // pixels per CTA
#define NCH   72              // K chunks of 32
#define NCOORD (TPIX*KKn)     // 576

// smem byte offsets
#define WH0   0u              // w hi buf0 [256][32] bf16 = 16384
#define WL0   16384u
#define WH1   32768u
#define WL1   49152u
#define SH0   65536u          // s hi buf0 [64][32] bf16 = 4096
#define SL0   69632u
#define SH1   73728u
#define SL1   77824u
#define CO_B  81920u
#define SMEM_BYTES (81920 + 3*NCOORD*4)   // 88832

// ---------------- scratch ----------------
__device__ float g_xt[Bn*HWn*Cn];        // x transposed to NHWC
__device__ float g_py [Bn*KKn*HWn];
__device__ float g_px [Bn*KKn*HWn];
__device__ float g_msk[Bn*KKn*HWn];
__device__ float g_wsoff[Cn*KKn*28];
__device__ __nv_bfloat16 g_whb[On*KDIM]; // w hi bf16 [o][kk*256+c]
__device__ __nv_bfloat16 g_wlb[On*KDIM]; // w lo bf16
__device__ float g_bnA[On];
__device__ float g_bnB[On];

// ---------------- helpers ----------------
__device__ __forceinline__ ull pk2(float a, float b) {
    ull r; asm("mov.b64 %0, {%1, %2};" : "=l"(r) : "f"(a), "f"(b)); return r;
}
__device__ __forceinline__ void unpk(ull v, float& a, float& b) {
    asm("mov.b64 {%0, %1}, %2;" : "=f"(a), "=f"(b) : "l"(v));
}
__device__ __forceinline__ void fma2(ull& d, ull a, ull b) {
    asm("fma.rn.f32x2 %0, %1, %2, %0;" : "+l"(d) : "l"(a), "l"(b));
}
__device__ __forceinline__ uint32_t smem_u32(const void* p) {
    return (uint32_t)__cvta_generic_to_shared(p);
}
__device__ __forceinline__ void cp16(uint32_t dst, const void* src) {
    asm volatile("cp.async.cg.shared.global [%0], [%1], 16;" :: "r"(dst), "l"(src));
}
#define CP_COMMIT()  asm volatile("cp.async.commit_group;")
#define CP_WAIT(n)   asm volatile("cp.async.wait_group %0;" :: "n"(n))

__device__ __forceinline__ void ldsm4(uint32_t* r, uint32_t addr) {
    asm volatile("ldmatrix.sync.aligned.m8n8.x4.shared.b16 {%0,%1,%2,%3}, [%4];"
        : "=r"(r[0]), "=r"(r[1]), "=r"(r[2]), "=r"(r[3]) : "r"(addr));
}
__device__ __forceinline__ void mma16816(float* d, const uint32_t* a, uint32_t b0, uint32_t b1) {
    asm volatile("mma.sync.aligned.m16n8k16.row.col.f32.bf16.bf16.f32 "
        "{%0,%1,%2,%3}, {%4,%5,%6,%7}, {%8,%9}, {%0,%1,%2,%3};"
        : "+f"(d[0]), "+f"(d[1]), "+f"(d[2]), "+f"(d[3])
        : "r"(a[0]), "r"(a[1]), "r"(a[2]), "r"(a[3]), "r"(b0), "r"(b1));
}

// ---------------- prep ----------------
__global__ void prep_kernel(const float* __restrict__ w_off,
                            const float* __restrict__ w_dcn,
                            const float* __restrict__ b_dcn,
                            const float* __restrict__ gamma,
                            const float* __restrict__ beta,
                            const float* __restrict__ rmean,
                            const float* __restrict__ rvar) {
    int t = blockIdx.x * blockDim.x + threadIdx.x;
    int stride = gridDim.x * blockDim.x;
    for (int i = t; i < Cn*KKn*28; i += stride) {
        int oc = i % 28; int rest = i / 28;
        int kk = rest % KKn; int c = rest / KKn;
        g_wsoff[i] = (oc < 27) ? w_off[(oc*Cn + c)*KKn + kk] : 0.f;
    }
    for (int i = t; i < On*KDIM; i += stride) {
        int K = i % KDIM; int o = i / KDIM;
        int kk = K / Cn;  int c = K % Cn;
        float v = w_dcn[(o*Cn + c)*KKn + kk];
        __nv_bfloat16 h = __float2bfloat16_rn(v);
        float hf = __bfloat162float(h);
        g_whb[i] = h;
        g_wlb[i] = __float2bfloat16_rn(v - hf);
    }
    if (t < On) {
        float inv = rsqrtf(rvar[t] + 1e-5f);
        float A = gamma[t] * inv;
        g_bnA[t] = A;
        g_bnB[t] = (b_dcn[t] - rmean[t]) * A + beta[t];
    }
}

// ---------------- NCHW -> NHWC transpose ----------------
__global__ void transpose_kernel(const float* __restrict__ x) {
    __shared__ float tile[32][33];
    int bh = blockIdx.z;
    int c0 = blockIdx.y * 32;
    int w0 = blockIdx.x * 32;
    int b = bh / Hn; int h = bh % Hn;
    for (int i = threadIdx.y; i < 32; i += 8)
        tile[i][threadIdx.x] = x[((b*Cn + c0 + i)*Hn + h)*Wn + w0 + threadIdx.x];
    __syncthreads();
    for (int i = threadIdx.y; i < 32; i += 8)
        g_xt[((size_t)(b*Hn + h)*Wn + w0 + i)*Cn + c0 + threadIdx.x] = tile[threadIdx.x][i];
}

// ---------------- offset conv (scalar, unchanged) ----------------
__global__ __launch_bounds__(128) void offset_kernel(const float* __restrict__ x,
                                                     const float* __restrict__ b_off) {
    __shared__ float ws[32*KKn*28];
    int pix = blockIdx.x * 128 + threadIdx.x;
    int b = pix / HWn; int hw = pix % HWn;
    int h = hw / Wn;   int w = hw % Wn;

    ull acc[14];
    #pragma unroll
    for (int q = 0; q < 14; q++) acc[q] = 0ull;

    for (int c0 = 0; c0 < Cn; c0 += 32) {
        __syncthreads();
        for (int i = threadIdx.x; i < 32*KKn*28; i += 128)
            ws[i] = g_wsoff[c0*KKn*28 + i];
        __syncthreads();
        for (int c = 0; c < 32; c++) {
            const float* xr = x + ((size_t)(b*Cn + c0 + c)*Hn)*Wn;
            #pragma unroll
            for (int kk = 0; kk < 9; kk++) {
                int dy = kk/3 - 1, dx = kk%3 - 1;
                int yy = h + dy, xx = w + dx;
                float xv = 0.f;
                if ((unsigned)yy < (unsigned)Hn && (unsigned)xx < (unsigned)Wn)
                    xv = xr[yy*Wn + xx];
                ull xv2 = pk2(xv, xv);
                const ulonglong2* wrow = (const ulonglong2*)(ws + (c*KKn + kk)*28);
                #pragma unroll
                for (int q = 0; q < 7; q++) {
                    ulonglong2 wv = wrow[q];
                    fma2(acc[2*q],   wv.x, xv2);
                    fma2(acc[2*q+1], wv.y, xv2);
                }
            }
        }
    }

    float v[28];
    #pragma unroll
    for (int q = 0; q < 14; q++) unpk(acc[q], v[2*q], v[2*q+1]);

    #pragma unroll
    for (int k = 0; k < 9; k++) {
        int dy = k/3 - 1, dx = k%3 - 1;
        float py = v[2*k]   + b_off[2*k]   + (float)(h + dy);
        float px = v[2*k+1] + b_off[2*k+1] + (float)(w + dx);
        float mv = v[18+k] + b_off[18+k];
        float mm = 1.f / (1.f + expf(-mv));
        int idx = (b*KKn + k)*HWn + hw;
        g_py[idx] = py; g_px[idx] = px; g_msk[idx] = mm;
    }
}

// ---------------- main: bf16 3-pass mma fused DCN ----------------
__device__ __forceinline__ float4 corner_ld(const float* __restrict__ xtb, int y, int x, int c4) {
    if ((unsigned)y < (unsigned)Hn && (unsigned)x < (unsigned)Wn)
        return *(const float4*)(xtb + ((y*Wn + x) << 8) + (c4 << 2));
    return make_float4(0.f, 0.f, 0.f, 0.f);
}

__device__ __forceinline__ uint32_t pack_bf_hi(float a, float b) {
    __nv_bfloat16 ha = __float2bfloat16_rn(a);
    __nv_bfloat16 hb = __float2bfloat16_rn(b);
    unsigned short ua = *(unsigned short*)&ha;
    unsigned short ub = *(unsigned short*)&hb;
    return (uint32_t)ua | ((uint32_t)ub << 16);
}
__device__ __forceinline__ uint32_t pack_bf_lo(float a, float b) {
    __nv_bfloat16 ha = __float2bfloat16_rn(a);
    __nv_bfloat16 hb = __float2bfloat16_rn(b);
    float ra = a - __bfloat162float(ha);
    float rb = b - __bfloat162float(hb);
    __nv_bfloat16 la = __float2bfloat16_rn(ra);
    __nv_bfloat16 lb = __float2bfloat16_rn(rb);
    unsigned short ua = *(unsigned short*)&la;
    unsigned short ub = *(unsigned short*)&lb;
    return (uint32_t)ua | ((uint32_t)ub << 16);
}

__global__ __launch_bounds__(NT) void main_kernel(float* __restrict__ out) {
    extern __shared__ char smc[];
    uint32_t sb = smem_u32(smc);
    float* spy = (float*)(smc + CO_B);
    float* spx = spy + NCOORD;
    float* smk = spx + NCOORD;

    int tid  = threadIdx.x;
    int lane = tid & 31;
    int wid  = tid >> 5;
    int pixb = blockIdx.x * TPIX;
    int b    = pixb / HWn;
    int hwb  = pixb % HWn;

    // coords
    for (int i = tid; i < NCOORD; i += NT) {
        int p = i / KKn, k = i % KKn;
        int gi = (b*KKn + k)*HWn + hwb + p;
        spy[i] = g_py[gi]; spx[i] = g_px[gi]; smk[i] = g_msk[gi];
    }
    __syncthreads();

    const float* xtb = g_xt + (size_t)b * (HWn*Cn);

    // gather task geometry (fixed per thread): p = tid>>2, cq = tid&3
    int gp  = tid >> 2;
    int gcq = tid & 3;
    uint32_t s_sw = (uint32_t)((gcq ^ ((gp >> 1) & 3)) << 4);
    uint32_t s_off = (uint32_t)gp*64u + s_sw;   // into sh buf; sl = +4096

    // w cp geometry: 8 chunks of 16B per thread per k-chunk
    // id = i*256 + tid: hilo = id>>10, o = (id>>2)&255, u = id&3

    // ---- helper lambdas (macros by hand) ----
    // prologue: cp w chunk 0, gather s chunk 0
    {
        #pragma unroll
        for (int i = 0; i < 8; i++) {
            int id = i*NT + tid;
            int hilo = id >> 10;
            int o = (id >> 2) & 255;
            int u = id & 3;
            const __nv_bfloat16* src = (hilo ? g_wlb : g_whb) + (size_t)o*KDIM + u*8;
            uint32_t dst = sb + (hilo ? WL0 : WH0) + (uint32_t)o*64u
                         + (uint32_t)(((u ^ ((o>>1)&3))) << 4);
            cp16(dst, src);
        }
        CP_COMMIT();
        // gather chunk 0: kk=0, c8 = gcq*8
        float py = spy[gp*KKn + 0], px = spx[gp*KKn + 0], mm = smk[gp*KKn + 0];
        float fy = floorf(py), fx = floorf(px);
        int y0 = (int)fy, x0 = (int)fx;
        float wy = py - fy, wx = px - fx;
        float w00 = (1.f-wy)*(1.f-wx), w01 = (1.f-wy)*wx;
        float w10 = wy*(1.f-wx),       w11 = wy*wx;
        uint4 hv, lv;
        uint32_t* hp = &hv.x; uint32_t* lp = &lv.x;
        #pragma unroll
        for (int g = 0; g < 2; g++) {
            int c4 = gcq*2 + g;
            float4 v00 = corner_ld(xtb, y0,   x0,   c4);
            float4 v01 = corner_ld(xtb, y0,   x0+1, c4);
            float4 v10 = corner_ld(xtb, y0+1, x0,   c4);
            float4 v11 = corner_ld(xtb, y0+1, x0+1, c4);
            float r0 = (v00.x*w00 + v01.x*w01 + v10.x*w10 + v11.x*w11) * mm;
            float r1 = (v00.y*w00 + v01.y*w01 + v10.y*w10 + v11.y*w11) * mm;
            float r2 = (v00.z*w00 + v01.z*w01 + v10.z*w10 + v11.z*w11) * mm;
            float r3 = (v00.w*w00 + v01.w*w01 + v10.w*w10 + v11.w*w11) * mm;
            hp[g*2]   = pack_bf_hi(r0, r1);
            hp[g*2+1] = pack_bf_hi(r2, r3);
            lp[g*2]   = pack_bf_lo(r0, r1);
            lp[g*2+1] = pack_bf_lo(r2, r3);
        }
        *(uint4*)(smc + SH0 + s_off) = hv;
        *(uint4*)(smc + SL0 + s_off) = lv;
    }

    // mma geometry
    int ob = (wid >> 1) * 64;
    int pb = (wid & 1) * 32;
    float acc[4][4][4];
    #pragma unroll
    for (int mt = 0; mt < 4; mt++)
        #pragma unroll
        for (int nt = 0; nt < 4; nt++)
            #pragma unroll
            for (int e = 0; e < 4; e++) acc[mt][nt][e] = 0.f;

    #pragma unroll 1
    for (int q = 0; q < NCH; q++) {
        int buf = q & 1;
        bool more = (q + 1 < NCH);

        // (a) cp w chunk q+1
        if (more) {
            int qn = q + 1;
            uint32_t wb_n = (qn & 1) ? WH1 : WH0;
            #pragma unroll
            for (int i = 0; i < 8; i++) {
                int id = i*NT + tid;
                int hilo = id >> 10;
                int o = (id >> 2) & 255;
                int u = id & 3;
                const __nv_bfloat16* src = (hilo ? g_wlb : g_whb)
                                         + (size_t)o*KDIM + qn*32 + u*8;
                uint32_t dst = sb + wb_n + (hilo ? 16384u : 0u) + (uint32_t)o*64u
                             + (uint32_t)(((u ^ ((o>>1)&3))) << 4);
                cp16(dst, src);
            }
            CP_COMMIT();
        }

        // (b) corner LDGs for s chunk q+1
        float4 C0[4], C1[4];
        float w00, w01, w10, w11, mmv;
        if (more) {
            int qn = q + 1;
            int kk = qn >> 3;
            int c4b = ((qn & 7) << 3) + gcq*2;
            float py = spy[gp*KKn + kk], px = spx[gp*KKn + kk];
            mmv = smk[gp*KKn + kk];
            float fy = floorf(py), fx = floorf(px);
            int y0 = (int)fy, x0 = (int)fx;
            float wy = py - fy, wx = px - fx;
            w00 = (1.f-wy)*(1.f-wx); w01 = (1.f-wy)*wx;
            w10 = wy*(1.f-wx);       w11 = wy*wx;
            C0[0] = corner_ld(xtb, y0,   x0,   c4b);
            C0[1] = corner_ld(xtb, y0,   x0+1, c4b);
            C0[2] = corner_ld(xtb, y0+1, x0,   c4b);
            C0[3] = corner_ld(xtb, y0+1, x0+1, c4b);
            C1[0] = corner_ld(xtb, y0,   x0,   c4b+1);
            C1[1] = corner_ld(xtb, y0,   x0+1, c4b+1);
            C1[2] = corner_ld(xtb, y0+1, x0,   c4b+1);
            C1[3] = corner_ld(xtb, y0+1, x0+1, c4b+1);
        }

        // (c)(d)
        if (more) { CP_WAIT(1); } else { CP_WAIT(0); }
        __syncthreads();

        // (e) MMA on chunk q
        {
            uint32_t whb = sb + (buf ? WH1 : WH0);
            uint32_t shb = sb + (buf ? SH1 : SH0);
            #pragma unroll
            for (int ks = 0; ks < 2; ks++) {
                uint32_t ah[4][4], al[4][4];
                #pragma unroll
                for (int mt = 0; mt < 4; mt++) {
                    int o = ob + mt*16 + (lane & 15);
                    int u = ks*2 + (lane >> 4);
                    uint32_t ad = whb + (uint32_t)o*64u
                                + (uint32_t)(((u ^ ((o>>1)&3))) << 4);
                    ldsm4(ah[mt], ad);
                    ldsm4(al[mt], ad + 16384u);
                }
                uint32_t bh[2][4], bl[2][4];
                #pragma unroll
                for (int np = 0; np < 2; np++) {
                    int p = pb + np*16 + (lane & 7) + ((lane >> 4) << 3);
                    int u = ks*2 + ((lane >> 3) & 1);
                    uint32_t bd = shb + (uint32_t)p*64u
                                + (uint32_t)(((u ^ ((p>>1)&3))) << 4);
                    ldsm4(bh[np], bd);
                    ldsm4(bl[np], bd + 4096u);
                }
                #pragma unroll
                for (int mt = 0; mt < 4; mt++)
                    #pragma unroll
                    for (int np = 0; np < 2; np++)
                        #pragma unroll
                        for (int hf = 0; hf < 2; hf++) {
                            int nt = np*2 + hf;
                            mma16816(acc[mt][nt], ah[mt], bh[np][hf*2], bh[np][hf*2+1]);
                            mma16816(acc[mt][nt], ah[mt], bl[np][hf*2], bl[np][hf*2+1]);
                            mma16816(acc[mt][nt], al[mt], bh[np][hf*2], bh[np][hf*2+1]);
                        }
            }
        }

        // (f) interp + STS for chunk q+1
        if (more) {
            uint32_t sdst = ((q+1) & 1) ? SH1 : SH0;
            uint4 hv, lv;
            uint32_t* hp = &hv.x; uint32_t* lp = &lv.x;
            {
                float r0 = (C0[0].x*w00 + C0[1].x*w01 + C0[2].x*w10 + C0[3].x*w11) * mmv;
                float r1 = (C0[0].y*w00 + C0[1].y*w01 + C0[2].y*w10 + C0[3].y*w11) * mmv;
                float r2 = (C0[0].z*w00 + C0[1].z*w01 + C0[2].z*w10 + C0[3].z*w11) * mmv;
                float r3 = (C0[0].w*w00 + C0[1].w*w01 + C0[2].w*w10 + C0[3].w*w11) * mmv;
                hp[0] = pack_bf_hi(r0, r1); hp[1] = pack_bf_hi(r2, r3);
                lp[0] = pack_bf_lo(r0, r1); lp[1] = pack_bf_lo(r2, r3);
            }
            {
                float r0 = (C1[0].x*w00 + C1[1].x*w01 + C1[2].x*w10 + C1[3].x*w11) * mmv;
                float r1 = (C1[0].y*w00 + C1[1].y*w01 + C1[2].y*w10 + C1[3].y*w11) * mmv;
                float r2 = (C1[0].z*w00 + C1[1].z*w01 + C1[2].z*w10 + C1[3].z*w11) * mmv;
                float r3 = (C1[0].w*w00 + C1[1].w*w01 + C1[2].w*w10 + C1[3].w*w11) * mmv;
                hp[2] = pack_bf_hi(r0, r1); hp[3] = pack_bf_hi(r2, r3);
                lp[2] = pack_bf_lo(r0, r1); lp[3] = pack_bf_lo(r2, r3);
            }
            *(uint4*)(smc + sdst + s_off) = hv;
            *(uint4*)(smc + sdst + 4096u + s_off) = lv;
        }

        // (g)
        __syncthreads();
    }

    // ---- epilogue: BN + ReLU ----
    int tg = lane & 3, g = lane >> 2;
    #pragma unroll
    for (int mt = 0; mt < 4; mt++) {
        int o0 = ob + mt*16 + g;
        int o1 = o0 + 8;
        float A0 = g_bnA[o0], B0 = g_bnB[o0];
        float A1 = g_bnA[o1], B1 = g_bnB[o1];
        float* r0 = out + ((size_t)(b*On + o0))*HWn + hwb;
        float* r1 = out + ((size_t)(b*On + o1))*HWn + hwb;
        #pragma unroll
        for (int nt = 0; nt < 4; nt++) {
            int p0 = pb + nt*8 + tg*2;
            float2 v0, v1;
            v0.x = fmaxf(acc[mt][nt][0]*A0 + B0, 0.f);
            v0.y = fmaxf(acc[mt][nt][1]*A0 + B0, 0.f);
            v1.x = fmaxf(acc[mt][nt][2]*A1 + B1, 0.f);
            v1.y = fmaxf(acc[mt][nt][3]*A1 + B1, 0.f);
            *(float2*)(r0 + p0) = v0;
            *(float2*)(r1 + p0) = v1;
        }
    }
}

// ---------------- launch ----------------
extern "C" void kernel_launch(void* const* d_in, const int* in_sizes, int n_in,
                              void* d_out, int out_size) {
    const float* x      = (const float*)d_in[0];
    const float* w_off  = (const float*)d_in[1];
    const float* b_off  = (const float*)d_in[2];
    const float* w_dcn  = (const float*)d_in[3];
    const float* b_dcn  = (const float*)d_in[4];
    const float* gamma  = (const float*)d_in[5];
    const float* beta   = (const float*)d_in[6];
    const float* rmean  = (const float*)d_in[7];
    const float* rvar   = (const float*)d_in[8];
    float* out = (float*)d_out;

    cudaFuncSetAttribute(main_kernel, cudaFuncAttributeMaxDynamicSharedMemorySize, SMEM_BYTES);
    cudaFuncSetAttribute(main_kernel, cudaFuncAttributePreferredSharedMemoryCarveout, 100);

    prep_kernel<<<256, 256>>>(w_off, w_dcn, b_dcn, gamma, beta, rmean, rvar);

    dim3 tgrid(Wn/32, Cn/32, Bn*Hn);
    transpose_kernel<<<tgrid, dim3(32, 8)>>>(x);

    offset_kernel<<<(Bn*HWn)/128, 128>>>(x, b_off);

    main_kernel<<<(Bn*HWn)/TPIX, NT, SMEM_BYTES>>>(out);
}

// round 11
// speedup vs baseline: 2.7555x; 1.4434x over previous
#include <cuda_runtime.h>
#include <cuda_bf16.h>
#include <cstdint>

typedef unsigned long long ull;

#define KKn  9
#define Bn   8
#define Cn   256
#define Hn   96
#define Wn   96
#define On   256
#define HWn  (Hn*Wn)          // 9216
#define KDIM (Cn*KKn)         // 2304

// ---- main mma kernel ----
#define NT    256
#define TPIX  64              // pixels per CTA
#define NCH   72              // K chunks of 32
#define NCOORD (TPIX*KKn)     // 576

// main smem byte offsets
#define WH0   0u
#define WL0   16384u
#define WH1   32768u
#define WL1   49152u
#define SH0   65536u
#define SL0   69632u
#define SH1   73728u
#define SL1   77824u
#define CO_B  81920u
#define SMEM_BYTES (81920 + 3*NCOORD*4)   // 88832 -> 2 blocks/SM

// ---- offset mma kernel ----
#define ONT   128
#define OTP   128             // pixels per CTA
#define OAH0  0u
#define OAL0  2048u
#define OAH1  4096u
#define OAL1  6144u
#define OBH0  8192u
#define OBL0  16384u
#define OBH1  24576u
#define OBL1  32768u
#define OV_B  40960u
#define OVSTR 132
#define OSMEM (40960 + 28*OVSTR*4)        // 55744

// ---------------- scratch ----------------
__device__ float g_xt[Bn*HWn*Cn];        // x transposed to NHWC
__device__ float g_py [Bn*KKn*HWn];
__device__ float g_px [Bn*KKn*HWn];
__device__ float g_msk[Bn*KKn*HWn];
__device__ __nv_bfloat16 g_whb[On*KDIM]; // main w hi bf16 [o][kk*256+c]
__device__ __nv_bfloat16 g_wlb[On*KDIM];
__device__ __nv_bfloat16 g_wohb[32*KDIM];// offset w hi bf16 [o pad32][kk*256+c]
__device__ __nv_bfloat16 g_wolb[32*KDIM];
__device__ float g_bnA[On];
__device__ float g_bnB[On];

// ---------------- helpers ----------------
__device__ __forceinline__ uint32_t smem_u32(const void* p) {
    return (uint32_t)__cvta_generic_to_shared(p);
}
__device__ __forceinline__ void cp16(uint32_t dst, const void* src) {
    asm volatile("cp.async.cg.shared.global [%0], [%1], 16;" :: "r"(dst), "l"(src));
}
#define CP_COMMIT()  asm volatile("cp.async.commit_group;")
#define CP_WAIT(n)   asm volatile("cp.async.wait_group %0;" :: "n"(n))

__device__ __forceinline__ void ldsm4(uint32_t* r, uint32_t addr) {
    asm volatile("ldmatrix.sync.aligned.m8n8.x4.shared.b16 {%0,%1,%2,%3}, [%4];"
        : "=r"(r[0]), "=r"(r[1]), "=r"(r[2]), "=r"(r[3]) : "r"(addr));
}
__device__ __forceinline__ void mma16816(float* d, const uint32_t* a, uint32_t b0, uint32_t b1) {
    asm volatile("mma.sync.aligned.m16n8k16.row.col.f32.bf16.bf16.f32 "
        "{%0,%1,%2,%3}, {%4,%5,%6,%7}, {%8,%9}, {%0,%1,%2,%3};"
        : "+f"(d[0]), "+f"(d[1]), "+f"(d[2]), "+f"(d[3])
        : "r"(a[0]), "r"(a[1]), "r"(a[2]), "r"(a[3]), "r"(b0), "r"(b1));
}
__device__ __forceinline__ uint32_t pack_bf_hi(float a, float b) {
    __nv_bfloat16 ha = __float2bfloat16_rn(a);
    __nv_bfloat16 hb = __float2bfloat16_rn(b);
    unsigned short ua = *(unsigned short*)&ha;
    unsigned short ub = *(unsigned short*)&hb;
    return (uint32_t)ua | ((uint32_t)ub << 16);
}
__device__ __forceinline__ uint32_t pack_bf_lo(float a, float b) {
    __nv_bfloat16 ha = __float2bfloat16_rn(a);
    __nv_bfloat16 hb = __float2bfloat16_rn(b);
    float ra = a - __bfloat162float(ha);
    float rb = b - __bfloat162float(hb);
    __nv_bfloat16 la = __float2bfloat16_rn(ra);
    __nv_bfloat16 lb = __float2bfloat16_rn(rb);
    unsigned short ua = *(unsigned short*)&la;
    unsigned short ub = *(unsigned short*)&lb;
    return (uint32_t)ua | ((uint32_t)ub << 16);
}

// ---------------- prep ----------------
__global__ void prep_kernel(const float* __restrict__ w_off,
                            const float* __restrict__ w_dcn,
                            const float* __restrict__ b_dcn,
                            const float* __restrict__ gamma,
                            const float* __restrict__ beta,
                            const float* __restrict__ rmean,
                            const float* __restrict__ rvar) {
    int t = blockIdx.x * blockDim.x + threadIdx.x;
    int stride = gridDim.x * blockDim.x;
    for (int i = t; i < On*KDIM; i += stride) {
        int K = i % KDIM; int o = i / KDIM;
        int kk = K / Cn;  int c = K % Cn;
        float v = w_dcn[(o*Cn + c)*KKn + kk];
        __nv_bfloat16 h = __float2bfloat16_rn(v);
        g_whb[i] = h;
        g_wlb[i] = __float2bfloat16_rn(v - __bfloat162float(h));
    }
    for (int i = t; i < 32*KDIM; i += stride) {
        int K = i % KDIM; int o = i / KDIM;
        int kk = K / Cn;  int c = K % Cn;
        float v = (o < 27) ? w_off[(o*Cn + c)*KKn + kk] : 0.f;
        __nv_bfloat16 h = __float2bfloat16_rn(v);
        g_wohb[i] = h;
        g_wolb[i] = __float2bfloat16_rn(v - __bfloat162float(h));
    }
    if (t < On) {
        float inv = rsqrtf(rvar[t] + 1e-5f);
        float A = gamma[t] * inv;
        g_bnA[t] = A;
        g_bnB[t] = (b_dcn[t] - rmean[t]) * A + beta[t];
    }
}

// ---------------- NCHW -> NHWC transpose ----------------
__global__ void transpose_kernel(const float* __restrict__ x) {
    __shared__ float tile[32][33];
    int bh = blockIdx.z;
    int c0 = blockIdx.y * 32;
    int w0 = blockIdx.x * 32;
    int b = bh / Hn; int h = bh % Hn;
    for (int i = threadIdx.y; i < 32; i += 8)
        tile[i][threadIdx.x] = x[((b*Cn + c0 + i)*Hn + h)*Wn + w0 + threadIdx.x];
    __syncthreads();
    for (int i = threadIdx.y; i < 32; i += 8)
        g_xt[((size_t)(b*Hn + h)*Wn + w0 + i)*Cn + c0 + threadIdx.x] = tile[threadIdx.x][i];
}

// ---------------- offset conv via bf16 3-pass mma ----------------
__global__ __launch_bounds__(ONT) void offset_mma_kernel(const float* __restrict__ b_off) {
    extern __shared__ char smc[];
    uint32_t sb = smem_u32(smc);
    float* ov = (float*)(smc + OV_B);

    int tid  = threadIdx.x;
    int lane = tid & 31;
    int wid  = tid >> 5;
    int pixb = blockIdx.x * OTP;
    int b    = pixb / HWn;
    int hwb  = pixb % HWn;
    const float* xtb = g_xt + (size_t)b * (HWn*Cn);

    // ---- B fill for chunk q into sel buffer (plain STS) ----
    auto fillB = [&](int q, uint32_t bh_off, uint32_t bl_off) {
        int kk = q >> 3;
        int c32 = (q & 7) * 32;
        int dy = kk/3 - 1, dx = kk%3 - 1;
        #pragma unroll
        for (int i = 0; i < 4; i++) {
            int t = i*ONT + tid;
            int p = t >> 2, quad = t & 3;
            int hw = hwb + p;
            int h = hw / Wn, w = hw % Wn;
            int y = h + dy, x = w + dx;
            float4 va = make_float4(0.f,0.f,0.f,0.f), vb = va;
            if ((unsigned)y < (unsigned)Hn && (unsigned)x < (unsigned)Wn) {
                const float* r = xtb + ((y*Wn + x) << 8) + c32 + quad*8;
                va = *(const float4*)r;
                vb = *(const float4*)(r + 4);
            }
            uint4 hv, lv;
            hv.x = pack_bf_hi(va.x, va.y); hv.y = pack_bf_hi(va.z, va.w);
            hv.z = pack_bf_hi(vb.x, vb.y); hv.w = pack_bf_hi(vb.z, vb.w);
            lv.x = pack_bf_lo(va.x, va.y); lv.y = pack_bf_lo(va.z, va.w);
            lv.z = pack_bf_lo(vb.x, vb.y); lv.w = pack_bf_lo(vb.z, vb.w);
            uint32_t off = (uint32_t)p*64u + (uint32_t)((quad ^ ((p>>1)&3)) << 4);
            *(uint4*)(smc + bh_off + off) = hv;
            *(uint4*)(smc + bl_off + off) = lv;
        }
    };
    // ---- A cp for chunk q ----
    auto cpA = [&](int q, uint32_t ah_off, uint32_t al_off) {
        #pragma unroll
        for (int i = 0; i < 2; i++) {
            int id = i*ONT + tid;          // 256 tasks
            int row = id >> 3;
            int quad = (id >> 1) & 3;
            int hilo = id & 1;
            const __nv_bfloat16* src = (hilo ? g_wolb : g_wohb)
                                     + (size_t)row*KDIM + q*32 + quad*8;
            uint32_t dst = sb + (hilo ? al_off : ah_off) + (uint32_t)row*64u
                         + (uint32_t)((quad ^ ((row>>1)&3)) << 4);
            cp16(dst, src);
        }
        CP_COMMIT();
    };

    cpA(0, OAH0, OAL0);
    fillB(0, OBH0, OBL0);

    int pb = wid * 32;
    float acc[2][4][4];
    #pragma unroll
    for (int mt = 0; mt < 2; mt++)
        #pragma unroll
        for (int nt = 0; nt < 4; nt++)
            #pragma unroll
            for (int e = 0; e < 4; e++) acc[mt][nt][e] = 0.f;

    #pragma unroll 1
    for (int q = 0; q < NCH; q++) {
        int buf = q & 1;
        bool more = (q + 1 < NCH);
        if (more) cpA(q+1, (q+1)&1 ? OAH1 : OAH0, (q+1)&1 ? OAL1 : OAL0);
        if (more) { CP_WAIT(1); } else { CP_WAIT(0); }
        __syncthreads();

        uint32_t ab = sb + (buf ? OAH1 : OAH0);
        uint32_t bb = sb + (buf ? OBH1 : OBH0);
        #pragma unroll
        for (int ks = 0; ks < 2; ks++) {
            uint32_t bh[2][4], bl[2][4];
            #pragma unroll
            for (int np = 0; np < 2; np++) {
                int p = pb + np*16 + (lane & 7) + ((lane >> 4) << 3);
                int u = ks*2 + ((lane >> 3) & 1);
                uint32_t bd = bb + (uint32_t)p*64u + (uint32_t)((u ^ ((p>>1)&3)) << 4);
                ldsm4(bh[np], bd);
                ldsm4(bl[np], bd + 8192u);
            }
            #pragma unroll
            for (int mt = 0; mt < 2; mt++) {
                int o = mt*16 + (lane & 15);
                int u = ks*2 + (lane >> 4);
                uint32_t ad = ab + (uint32_t)o*64u + (uint32_t)((u ^ ((o>>1)&3)) << 4);
                uint32_t ah[4], al[4];
                ldsm4(ah, ad);
                ldsm4(al, ad + 2048u);
                #pragma unroll
                for (int np = 0; np < 2; np++)
                    #pragma unroll
                    for (int hf = 0; hf < 2; hf++) {
                        int nt = np*2 + hf;
                        mma16816(acc[mt][nt], ah, bh[np][hf*2], bh[np][hf*2+1]);
                        mma16816(acc[mt][nt], ah, bl[np][hf*2], bl[np][hf*2+1]);
                        mma16816(acc[mt][nt], al, bh[np][hf*2], bh[np][hf*2+1]);
                    }
            }
        }

        if (more) fillB(q+1, (q+1)&1 ? OBH1 : OBH0, (q+1)&1 ? OBL1 : OBL0);
        __syncthreads();
    }

    // ---- write acc to ov ----
    #pragma unroll
    for (int mt = 0; mt < 2; mt++) {
        int o0 = mt*16 + (lane >> 2);
        int o1 = o0 + 8;
        #pragma unroll
        for (int nt = 0; nt < 4; nt++) {
            int p = pb + nt*8 + (lane & 3)*2;
            if (o0 < 27) {
                ov[o0*OVSTR + p]   = acc[mt][nt][0];
                ov[o0*OVSTR + p+1] = acc[mt][nt][1];
            }
            if (o1 < 27) {
                ov[o1*OVSTR + p]   = acc[mt][nt][2];
                ov[o1*OVSTR + p+1] = acc[mt][nt][3];
            }
        }
    }
    __syncthreads();

    // ---- epilogue: py/px/mask ----
    {
        int p = tid;
        int hw = hwb + p;
        int h = hw / Wn, w = hw % Wn;
        #pragma unroll
        for (int k = 0; k < KKn; k++) {
            float py = ov[(2*k)*OVSTR + p]   + b_off[2*k]   + (float)(h + k/3 - 1);
            float px = ov[(2*k+1)*OVSTR + p] + b_off[2*k+1] + (float)(w + k%3 - 1);
            float mv = ov[(18+k)*OVSTR + p]  + b_off[18+k];
            float mm = 1.f / (1.f + expf(-mv));
            int idx = (b*KKn + k)*HWn + hw;
            g_py[idx] = py; g_px[idx] = px; g_msk[idx] = mm;
        }
    }
}

// ---------------- main: bf16 3-pass mma fused DCN ----------------
__device__ __forceinline__ float4 corner_ld(const float* __restrict__ xtb, int y, int x, int c4) {
    if ((unsigned)y < (unsigned)Hn && (unsigned)x < (unsigned)Wn)
        return *(const float4*)(xtb + ((y*Wn + x) << 8) + (c4 << 2));
    return make_float4(0.f, 0.f, 0.f, 0.f);
}

__global__ __launch_bounds__(NT, 2) void main_kernel(float* __restrict__ out) {
    extern __shared__ char smc[];
    uint32_t sb = smem_u32(smc);
    float* spy = (float*)(smc + CO_B);
    float* spx = spy + NCOORD;
    float* smk = spx + NCOORD;

    int tid  = threadIdx.x;
    int lane = tid & 31;
    int wid  = tid >> 5;
    int pixb = blockIdx.x * TPIX;
    int b    = pixb / HWn;
    int hwb  = pixb % HWn;

    for (int i = tid; i < NCOORD; i += NT) {
        int p = i / KKn, k = i % KKn;
        int gi = (b*KKn + k)*HWn + hwb + p;
        spy[i] = g_py[gi]; spx[i] = g_px[gi]; smk[i] = g_msk[gi];
    }
    __syncthreads();

    const float* xtb = g_xt + (size_t)b * (HWn*Cn);

    int gp  = tid >> 2;
    int gcq = tid & 3;
    uint32_t s_off = (uint32_t)gp*64u + (uint32_t)((gcq ^ ((gp >> 1) & 3)) << 4);

    // gather s chunk q into buffer (q&1)
    auto gatherS = [&](int q) {
        int kk = q >> 3;
        int c4b = ((q & 7) << 3) + gcq*2;
        uint32_t sdst = (q & 1) ? SH1 : SH0;
        float py = spy[gp*KKn + kk], px = spx[gp*KKn + kk], mm = smk[gp*KKn + kk];
        float fy = floorf(py), fx = floorf(px);
        int y0 = (int)fy, x0 = (int)fx;
        float wy = py - fy, wx = px - fx;
        float w00 = (1.f-wy)*(1.f-wx), w01 = (1.f-wy)*wx;
        float w10 = wy*(1.f-wx),       w11 = wy*wx;
        uint4 hv, lv;
        uint32_t* hp = &hv.x; uint32_t* lp = &lv.x;
        #pragma unroll
        for (int g = 0; g < 2; g++) {
            int c4 = c4b + g;
            float4 v00 = corner_ld(xtb, y0,   x0,   c4);
            float4 v01 = corner_ld(xtb, y0,   x0+1, c4);
            float4 v10 = corner_ld(xtb, y0+1, x0,   c4);
            float4 v11 = corner_ld(xtb, y0+1, x0+1, c4);
            float r0 = (v00.x*w00 + v01.x*w01 + v10.x*w10 + v11.x*w11) * mm;
            float r1 = (v00.y*w00 + v01.y*w01 + v10.y*w10 + v11.y*w11) * mm;
            float r2 = (v00.z*w00 + v01.z*w01 + v10.z*w10 + v11.z*w11) * mm;
            float r3 = (v00.w*w00 + v01.w*w01 + v10.w*w10 + v11.w*w11) * mm;
            hp[g*2]   = pack_bf_hi(r0, r1);
            hp[g*2+1] = pack_bf_hi(r2, r3);
            lp[g*2]   = pack_bf_lo(r0, r1);
            lp[g*2+1] = pack_bf_lo(r2, r3);
        }
        *(uint4*)(smc + sdst + s_off) = hv;
        *(uint4*)(smc + sdst + 4096u + s_off) = lv;
    };
    // cp w chunk q into buffer (q&1)
    auto cpW = [&](int q) {
        uint32_t wb = (q & 1) ? WH1 : WH0;
        #pragma unroll
        for (int i = 0; i < 8; i++) {
            int id = i*NT + tid;
            int hilo = id >> 10;
            int o = (id >> 2) & 255;
            int u = id & 3;
            const __nv_bfloat16* src = (hilo ? g_wlb : g_whb)
                                     + (size_t)o*KDIM + q*32 + u*8;
            uint32_t dst = sb + wb + (hilo ? 16384u : 0u) + (uint32_t)o*64u
                         + (uint32_t)((u ^ ((o>>1)&3)) << 4);
            cp16(dst, src);
        }
        CP_COMMIT();
    };

    // prologue
    cpW(0);
    gatherS(0);

    int ob = (wid >> 1) * 64;
    int pb = (wid & 1) * 32;
    float acc[4][4][4];
    #pragma unroll
    for (int mt = 0; mt < 4; mt++)
        #pragma unroll
        for (int nt = 0; nt < 4; nt++)
            #pragma unroll
            for (int e = 0; e < 4; e++) acc[mt][nt][e] = 0.f;

    #pragma unroll 1
    for (int q = 0; q < NCH; q++) {
        int buf = q & 1;
        bool more = (q + 1 < NCH);

        if (more) cpW(q+1);
        if (more) { CP_WAIT(1); } else { CP_WAIT(0); }
        __syncthreads();

        // MMA on chunk q (low register pressure: per-mt A frags)
        {
            uint32_t whb = sb + (buf ? WH1 : WH0);
            uint32_t shb = sb + (buf ? SH1 : SH0);
            #pragma unroll
            for (int ks = 0; ks < 2; ks++) {
                uint32_t bh[2][4], bl[2][4];
                #pragma unroll
                for (int np = 0; np < 2; np++) {
                    int p = pb + np*16 + (lane & 7) + ((lane >> 4) << 3);
                    int u = ks*2 + ((lane >> 3) & 1);
                    uint32_t bd = shb + (uint32_t)p*64u + (uint32_t)((u ^ ((p>>1)&3)) << 4);
                    ldsm4(bh[np], bd);
                    ldsm4(bl[np], bd + 4096u);
                }
                #pragma unroll
                for (int mt = 0; mt < 4; mt++) {
                    int o = ob + mt*16 + (lane & 15);
                    int u = ks*2 + (lane >> 4);
                    uint32_t ad = whb + (uint32_t)o*64u + (uint32_t)((u ^ ((o>>1)&3)) << 4);
                    uint32_t ah[4], al[4];
                    ldsm4(ah, ad);
                    ldsm4(al, ad + 16384u);
                    #pragma unroll
                    for (int np = 0; np < 2; np++)
                        #pragma unroll
                        for (int hf = 0; hf < 2; hf++) {
                            int nt = np*2 + hf;
                            mma16816(acc[mt][nt], ah, bh[np][hf*2], bh[np][hf*2+1]);
                            mma16816(acc[mt][nt], ah, bl[np][hf*2], bl[np][hf*2+1]);
                            mma16816(acc[mt][nt], al, bh[np][hf*2], bh[np][hf*2+1]);
                        }
                }
            }
        }

        if (more) gatherS(q+1);
        __syncthreads();
    }

    // ---- epilogue: BN + ReLU ----
    int tg = lane & 3, g = lane >> 2;
    #pragma unroll
    for (int mt = 0; mt < 4; mt++) {
        int o0 = ob + mt*16 + g;
        int o1 = o0 + 8;
        float A0 = g_bnA[o0], B0 = g_bnB[o0];
        float A1 = g_bnA[o1], B1 = g_bnB[o1];
        float* r0 = out + ((size_t)(b*On + o0))*HWn + hwb;
        float* r1 = out + ((size_t)(b*On + o1))*HWn + hwb;
        #pragma unroll
        for (int nt = 0; nt < 4; nt++) {
            int p0 = pb + nt*8 + tg*2;
            float2 v0, v1;
            v0.x = fmaxf(acc[mt][nt][0]*A0 + B0, 0.f);
            v0.y = fmaxf(acc[mt][nt][1]*A0 + B0, 0.f);
            v1.x = fmaxf(acc[mt][nt][2]*A1 + B1, 0.f);
            v1.y = fmaxf(acc[mt][nt][3]*A1 + B1, 0.f);
            *(float2*)(r0 + p0) = v0;
            *(float2*)(r1 + p0) = v1;
        }
    }
}

// ---------------- launch ----------------
extern "C" void kernel_launch(void* const* d_in, const int* in_sizes, int n_in,
                              void* d_out, int out_size) {
    const float* x      = (const float*)d_in[0];
    const float* w_off  = (const float*)d_in[1];
    const float* b_off  = (const float*)d_in[2];
    const float* w_dcn  = (const float*)d_in[3];
    const float* b_dcn  = (const float*)d_in[4];
    const float* gamma  = (const float*)d_in[5];
    const float* beta   = (const float*)d_in[6];
    const float* rmean  = (const float*)d_in[7];
    const float* rvar   = (const float*)d_in[8];
    float* out = (float*)d_out;

    cudaFuncSetAttribute(main_kernel, cudaFuncAttributeMaxDynamicSharedMemorySize, SMEM_BYTES);
    cudaFuncSetAttribute(main_kernel, cudaFuncAttributePreferredSharedMemoryCarveout, 100);
    cudaFuncSetAttribute(offset_mma_kernel, cudaFuncAttributeMaxDynamicSharedMemorySize, OSMEM);

    prep_kernel<<<256, 256>>>(w_off, w_dcn, b_dcn, gamma, beta, rmean, rvar);

    dim3 tgrid(Wn/32, Cn/32, Bn*Hn);
    transpose_kernel<<<tgrid, dim3(32, 8)>>>(x);

    offset_mma_kernel<<<(Bn*HWn)/OTP, ONT, OSMEM>>>(b_off);

    main_kernel<<<(Bn*HWn)/TPIX, NT, SMEM_BYTES>>>(out);
}

// round 12
// speedup vs baseline: 3.2463x; 1.1781x over previous
#include <cuda_runtime.h>
#include <cuda_fp16.h>
#include <cstdint>

typedef unsigned long long ull;

#define KKn  9
#define Bn   8
#define Cn   256
#define Hn   96
#define Wn   96
#define On   256
#define HWn  (Hn*Wn)          // 9216
#define KDIM (Cn*KKn)         // 2304

// ---- main mma kernel ----
#define NT    256
#define TPIX  64              // pixels per CTA
#define NCH   72              // K chunks of 32
#define NCOORD (TPIX*KKn)     // 576

// main smem byte offsets (fp16 2-pass: w hi only; s hi+lo)
#define WH0   0u              // [256][32] fp16 = 16384
#define WH1   16384u
#define SH0   32768u          // [64][32] fp16 = 4096
#define SL0   36864u
#define SH1   40960u
#define SL1   45056u
#define CO_B  49152u
#define SMEM_BYTES (49152 + 3*NCOORD*4)   // 56064 -> 2 blocks/SM

// ---- offset mma kernel ----
#define ONT   128
#define OTP   128             // pixels per CTA
#define OAH0  0u              // [32][32] fp16 = 2048
#define OAH1  2048u
#define OBH0  4096u           // [128][32] fp16 = 8192
#define OBL0  12288u
#define OBH1  20480u
#define OBL1  28672u
#define OV_B  36864u
#define OVSTR 132
#define OSMEM (36864 + 28*OVSTR*4)        // 51648

// ---------------- scratch ----------------
__device__ float g_xt[Bn*HWn*Cn];        // x transposed to NHWC
__device__ float g_py [Bn*KKn*HWn];
__device__ float g_px [Bn*KKn*HWn];
__device__ float g_msk[Bn*KKn*HWn];
__device__ __half g_wh [On*KDIM];        // main w fp16 [o][kk*256+c]
__device__ __half g_woh[32*KDIM];        // offset w fp16 [o pad32][kk*256+c]
__device__ float g_bnA[On];
__device__ float g_bnB[On];

// ---------------- helpers ----------------
__device__ __forceinline__ uint32_t smem_u32(const void* p) {
    return (uint32_t)__cvta_generic_to_shared(p);
}
__device__ __forceinline__ void cp16(uint32_t dst, const void* src) {
    asm volatile("cp.async.cg.shared.global [%0], [%1], 16;" :: "r"(dst), "l"(src));
}
#define CP_COMMIT()  asm volatile("cp.async.commit_group;")
#define CP_WAIT(n)   asm volatile("cp.async.wait_group %0;" :: "n"(n))

__device__ __forceinline__ void ldsm4(uint32_t* r, uint32_t addr) {
    asm volatile("ldmatrix.sync.aligned.m8n8.x4.shared.b16 {%0,%1,%2,%3}, [%4];"
        : "=r"(r[0]), "=r"(r[1]), "=r"(r[2]), "=r"(r[3]) : "r"(addr));
}
__device__ __forceinline__ void mma_h(float* d, const uint32_t* a, uint32_t b0, uint32_t b1) {
    asm volatile("mma.sync.aligned.m16n8k16.row.col.f32.f16.f16.f32 "
        "{%0,%1,%2,%3}, {%4,%5,%6,%7}, {%8,%9}, {%0,%1,%2,%3};"
        : "+f"(d[0]), "+f"(d[1]), "+f"(d[2]), "+f"(d[3])
        : "r"(a[0]), "r"(a[1]), "r"(a[2]), "r"(a[3]), "r"(b0), "r"(b1));
}
__device__ __forceinline__ uint32_t pack_h_hi(float a, float b) {
    __half2 h = __floats2half2_rn(a, b);
    return *(uint32_t*)&h;
}
__device__ __forceinline__ uint32_t pack_h_lo(float a, float b) {
    float ra = a - __half2float(__float2half_rn(a));
    float rb = b - __half2float(__float2half_rn(b));
    __half2 h = __floats2half2_rn(ra, rb);
    return *(uint32_t*)&h;
}

// ---------------- prep ----------------
__global__ void prep_kernel(const float* __restrict__ w_off,
                            const float* __restrict__ w_dcn,
                            const float* __restrict__ b_dcn,
                            const float* __restrict__ gamma,
                            const float* __restrict__ beta,
                            const float* __restrict__ rmean,
                            const float* __restrict__ rvar) {
    int t = blockIdx.x * blockDim.x + threadIdx.x;
    int stride = gridDim.x * blockDim.x;
    for (int i = t; i < On*KDIM; i += stride) {
        int K = i % KDIM; int o = i / KDIM;
        int kk = K / Cn;  int c = K % Cn;
        g_wh[i] = __float2half_rn(w_dcn[(o*Cn + c)*KKn + kk]);
    }
    for (int i = t; i < 32*KDIM; i += stride) {
        int K = i % KDIM; int o = i / KDIM;
        int kk = K / Cn;  int c = K % Cn;
        float v = (o < 27) ? w_off[(o*Cn + c)*KKn + kk] : 0.f;
        g_woh[i] = __float2half_rn(v);
    }
    if (t < On) {
        float inv = rsqrtf(rvar[t] + 1e-5f);
        float A = gamma[t] * inv;
        g_bnA[t] = A;
        g_bnB[t] = (b_dcn[t] - rmean[t]) * A + beta[t];
    }
}

// ---------------- NCHW -> NHWC transpose ----------------
__global__ void transpose_kernel(const float* __restrict__ x) {
    __shared__ float tile[32][33];
    int bh = blockIdx.z;
    int c0 = blockIdx.y * 32;
    int w0 = blockIdx.x * 32;
    int b = bh / Hn; int h = bh % Hn;
    for (int i = threadIdx.y; i < 32; i += 8)
        tile[i][threadIdx.x] = x[((b*Cn + c0 + i)*Hn + h)*Wn + w0 + threadIdx.x];
    __syncthreads();
    for (int i = threadIdx.y; i < 32; i += 8)
        g_xt[((size_t)(b*Hn + h)*Wn + w0 + i)*Cn + c0 + threadIdx.x] = tile[threadIdx.x][i];
}

// ---------------- offset conv via fp16 2-pass mma ----------------
__global__ __launch_bounds__(ONT) void offset_mma_kernel(const float* __restrict__ b_off) {
    extern __shared__ char smc[];
    uint32_t sb = smem_u32(smc);
    float* ov = (float*)(smc + OV_B);

    int tid  = threadIdx.x;
    int lane = tid & 31;
    int wid  = tid >> 5;
    int pixb = blockIdx.x * OTP;
    int b    = pixb / HWn;
    int hwb  = pixb % HWn;
    const float* xtb = g_xt + (size_t)b * (HWn*Cn);

    auto fillB = [&](int q, uint32_t bh_off, uint32_t bl_off) {
        int kk = q >> 3;
        int c32 = (q & 7) * 32;
        int dy = kk/3 - 1, dx = kk%3 - 1;
        #pragma unroll
        for (int i = 0; i < 4; i++) {
            int t = i*ONT + tid;
            int p = t >> 2, quad = t & 3;
            int hw = hwb + p;
            int h = hw / Wn, w = hw % Wn;
            int y = h + dy, x = w + dx;
            float4 va = make_float4(0.f,0.f,0.f,0.f), vb = va;
            if ((unsigned)y < (unsigned)Hn && (unsigned)x < (unsigned)Wn) {
                const float* r = xtb + ((y*Wn + x) << 8) + c32 + quad*8;
                va = *(const float4*)r;
                vb = *(const float4*)(r + 4);
            }
            uint4 hv, lv;
            hv.x = pack_h_hi(va.x, va.y); hv.y = pack_h_hi(va.z, va.w);
            hv.z = pack_h_hi(vb.x, vb.y); hv.w = pack_h_hi(vb.z, vb.w);
            lv.x = pack_h_lo(va.x, va.y); lv.y = pack_h_lo(va.z, va.w);
            lv.z = pack_h_lo(vb.x, vb.y); lv.w = pack_h_lo(vb.z, vb.w);
            uint32_t off = (uint32_t)p*64u + (uint32_t)((quad ^ ((p>>1)&3)) << 4);
            *(uint4*)(smc + bh_off + off) = hv;
            *(uint4*)(smc + bl_off + off) = lv;
        }
    };
    auto cpA = [&](int q, uint32_t ah_off) {
        int row = tid >> 2;
        int quad = tid & 3;
        const __half* src = g_woh + (size_t)row*KDIM + q*32 + quad*8;
        uint32_t dst = sb + ah_off + (uint32_t)row*64u
                     + (uint32_t)((quad ^ ((row>>1)&3)) << 4);
        cp16(dst, src);
        CP_COMMIT();
    };

    cpA(0, OAH0);
    fillB(0, OBH0, OBL0);

    int pb = wid * 32;
    float acc[2][4][4];
    #pragma unroll
    for (int mt = 0; mt < 2; mt++)
        #pragma unroll
        for (int nt = 0; nt < 4; nt++)
            #pragma unroll
            for (int e = 0; e < 4; e++) acc[mt][nt][e] = 0.f;

    #pragma unroll 1
    for (int q = 0; q < NCH; q++) {
        int buf = q & 1;
        bool more = (q + 1 < NCH);
        if (more) cpA(q+1, (q+1)&1 ? OAH1 : OAH0);
        if (more) { CP_WAIT(1); } else { CP_WAIT(0); }
        __syncthreads();

        uint32_t ab = sb + (buf ? OAH1 : OAH0);
        uint32_t bb = sb + (buf ? OBH1 : OBH0);
        #pragma unroll
        for (int ks = 0; ks < 2; ks++) {
            uint32_t bh[2][4], bl[2][4];
            #pragma unroll
            for (int np = 0; np < 2; np++) {
                int p = pb + np*16 + (lane & 7) + ((lane >> 4) << 3);
                int u = ks*2 + ((lane >> 3) & 1);
                uint32_t bd = bb + (uint32_t)p*64u + (uint32_t)((u ^ ((p>>1)&3)) << 4);
                ldsm4(bh[np], bd);
                ldsm4(bl[np], bd + 8192u);
            }
            #pragma unroll
            for (int mt = 0; mt < 2; mt++) {
                int o = mt*16 + (lane & 15);
                int u = ks*2 + (lane >> 4);
                uint32_t ad = ab + (uint32_t)o*64u + (uint32_t)((u ^ ((o>>1)&3)) << 4);
                uint32_t ah[4];
                ldsm4(ah, ad);
                #pragma unroll
                for (int np = 0; np < 2; np++)
                    #pragma unroll
                    for (int hf = 0; hf < 2; hf++) {
                        int nt = np*2 + hf;
                        mma_h(acc[mt][nt], ah, bh[np][hf*2], bh[np][hf*2+1]);
                        mma_h(acc[mt][nt], ah, bl[np][hf*2], bl[np][hf*2+1]);
                    }
            }
        }

        if (more) fillB(q+1, (q+1)&1 ? OBH1 : OBH0, (q+1)&1 ? OBL1 : OBL0);
        __syncthreads();
    }

    // ---- write acc to ov ----
    #pragma unroll
    for (int mt = 0; mt < 2; mt++) {
        int o0 = mt*16 + (lane >> 2);
        int o1 = o0 + 8;
        #pragma unroll
        for (int nt = 0; nt < 4; nt++) {
            int p = pb + nt*8 + (lane & 3)*2;
            if (o0 < 27) {
                ov[o0*OVSTR + p]   = acc[mt][nt][0];
                ov[o0*OVSTR + p+1] = acc[mt][nt][1];
            }
            if (o1 < 27) {
                ov[o1*OVSTR + p]   = acc[mt][nt][2];
                ov[o1*OVSTR + p+1] = acc[mt][nt][3];
            }
        }
    }
    __syncthreads();

    // ---- epilogue: py/px/mask ----
    {
        int p = tid;
        int hw = hwb + p;
        int h = hw / Wn, w = hw % Wn;
        #pragma unroll
        for (int k = 0; k < KKn; k++) {
            float py = ov[(2*k)*OVSTR + p]   + b_off[2*k]   + (float)(h + k/3 - 1);
            float px = ov[(2*k+1)*OVSTR + p] + b_off[2*k+1] + (float)(w + k%3 - 1);
            float mv = ov[(18+k)*OVSTR + p]  + b_off[18+k];
            float mm = 1.f / (1.f + expf(-mv));
            int idx = (b*KKn + k)*HWn + hw;
            g_py[idx] = py; g_px[idx] = px; g_msk[idx] = mm;
        }
    }
}

// ---------------- main: fp16 2-pass mma fused DCN ----------------
__device__ __forceinline__ float4 corner_ld(const float* __restrict__ xtb, int y, int x, int c4) {
    if ((unsigned)y < (unsigned)Hn && (unsigned)x < (unsigned)Wn)
        return *(const float4*)(xtb + ((y*Wn + x) << 8) + (c4 << 2));
    return make_float4(0.f, 0.f, 0.f, 0.f);
}

__global__ __launch_bounds__(NT, 2) void main_kernel(float* __restrict__ out) {
    extern __shared__ char smc[];
    uint32_t sb = smem_u32(smc);
    float* spy = (float*)(smc + CO_B);
    float* spx = spy + NCOORD;
    float* smk = spx + NCOORD;

    int tid  = threadIdx.x;
    int lane = tid & 31;
    int wid  = tid >> 5;
    int pixb = blockIdx.x * TPIX;
    int b    = pixb / HWn;
    int hwb  = pixb % HWn;

    for (int i = tid; i < NCOORD; i += NT) {
        int p = i / KKn, k = i % KKn;
        int gi = (b*KKn + k)*HWn + hwb + p;
        spy[i] = g_py[gi]; spx[i] = g_px[gi]; smk[i] = g_msk[gi];
    }
    __syncthreads();

    const float* xtb = g_xt + (size_t)b * (HWn*Cn);

    int gp  = tid >> 2;
    int gcq = tid & 3;
    uint32_t s_off = (uint32_t)gp*64u + (uint32_t)((gcq ^ ((gp >> 1) & 3)) << 4);

    auto cpW = [&](int q) {
        uint32_t wb = (q & 1) ? WH1 : WH0;
        #pragma unroll
        for (int i = 0; i < 4; i++) {
            int id = i*NT + tid;
            int o = id >> 2;
            int u = id & 3;
            const __half* src = g_wh + (size_t)o*KDIM + q*32 + u*8;
            uint32_t dst = sb + wb + (uint32_t)o*64u
                         + (uint32_t)((u ^ ((o>>1)&3)) << 4);
            cp16(dst, src);
        }
        CP_COMMIT();
    };

    // full gather of s chunk 0 (prologue)
    {
        cpW(0);
        int c4b = gcq*2;
        float py = spy[gp*KKn], px = spx[gp*KKn], mm = smk[gp*KKn];
        float fy = floorf(py), fx = floorf(px);
        int y0 = (int)fy, x0 = (int)fx;
        float wy = py - fy, wx = px - fx;
        float w00 = (1.f-wy)*(1.f-wx), w01 = (1.f-wy)*wx;
        float w10 = wy*(1.f-wx),       w11 = wy*wx;
        uint4 hv, lv;
        uint32_t* hp = &hv.x; uint32_t* lp = &lv.x;
        #pragma unroll
        for (int g = 0; g < 2; g++) {
            int c4 = c4b + g;
            float4 v00 = corner_ld(xtb, y0,   x0,   c4);
            float4 v01 = corner_ld(xtb, y0,   x0+1, c4);
            float4 v10 = corner_ld(xtb, y0+1, x0,   c4);
            float4 v11 = corner_ld(xtb, y0+1, x0+1, c4);
            float r0 = (v00.x*w00 + v01.x*w01 + v10.x*w10 + v11.x*w11) * mm;
            float r1 = (v00.y*w00 + v01.y*w01 + v10.y*w10 + v11.y*w11) * mm;
            float r2 = (v00.z*w00 + v01.z*w01 + v10.z*w10 + v11.z*w11) * mm;
            float r3 = (v00.w*w00 + v01.w*w01 + v10.w*w10 + v11.w*w11) * mm;
            hp[g*2]   = pack_h_hi(r0, r1);
            hp[g*2+1] = pack_h_hi(r2, r3);
            lp[g*2]   = pack_h_lo(r0, r1);
            lp[g*2+1] = pack_h_lo(r2, r3);
        }
        *(uint4*)(smc + SH0 + s_off) = hv;
        *(uint4*)(smc + SL0 + s_off) = lv;
    }

    int ob = (wid >> 1) * 64;
    int pb = (wid & 1) * 32;
    float acc[4][4][4];
    #pragma unroll
    for (int mt = 0; mt < 4; mt++)
        #pragma unroll
        for (int nt = 0; nt < 4; nt++)
            #pragma unroll
            for (int e = 0; e < 4; e++) acc[mt][nt][e] = 0.f;

    #pragma unroll 1
    for (int q = 0; q < NCH; q++) {
        int buf = q & 1;
        bool more = (q + 1 < NCH);

        if (more) cpW(q+1);

        // ---- pre-issue corner LDGs for s chunk q+1 (covered by MMA below) ----
        float4 C0[4], C1[4];
        float w00, w01, w10, w11, mmv;
        if (more) {
            int qn = q + 1;
            int kk = qn >> 3;
            int c4b = ((qn & 7) << 3) + gcq*2;
            float py = spy[gp*KKn + kk], px = spx[gp*KKn + kk];
            mmv = smk[gp*KKn + kk];
            float fy = floorf(py), fx = floorf(px);
            int y0 = (int)fy, x0 = (int)fx;
            float wy = py - fy, wx = px - fx;
            w00 = (1.f-wy)*(1.f-wx); w01 = (1.f-wy)*wx;
            w10 = wy*(1.f-wx);       w11 = wy*wx;
            C0[0] = corner_ld(xtb, y0,   x0,   c4b);
            C0[1] = corner_ld(xtb, y0,   x0+1, c4b);
            C0[2] = corner_ld(xtb, y0+1, x0,   c4b);
            C0[3] = corner_ld(xtb, y0+1, x0+1, c4b);
            C1[0] = corner_ld(xtb, y0,   x0,   c4b+1);
            C1[1] = corner_ld(xtb, y0,   x0+1, c4b+1);
            C1[2] = corner_ld(xtb, y0+1, x0,   c4b+1);
            C1[3] = corner_ld(xtb, y0+1, x0+1, c4b+1);
        }

        if (more) { CP_WAIT(1); } else { CP_WAIT(0); }
        __syncthreads();

        // ---- MMA on chunk q ----
        {
            uint32_t whb = sb + (buf ? WH1 : WH0);
            uint32_t shb = sb + (buf ? SH1 : SH0);
            #pragma unroll
            for (int ks = 0; ks < 2; ks++) {
                uint32_t bh[2][4], bl[2][4];
                #pragma unroll
                for (int np = 0; np < 2; np++) {
                    int p = pb + np*16 + (lane & 7) + ((lane >> 4) << 3);
                    int u = ks*2 + ((lane >> 3) & 1);
                    uint32_t bd = shb + (uint32_t)p*64u + (uint32_t)((u ^ ((p>>1)&3)) << 4);
                    ldsm4(bh[np], bd);
                    ldsm4(bl[np], bd + 4096u);
                }
                #pragma unroll
                for (int mt = 0; mt < 4; mt++) {
                    int o = ob + mt*16 + (lane & 15);
                    int u = ks*2 + (lane >> 4);
                    uint32_t ad = whb + (uint32_t)o*64u + (uint32_t)((u ^ ((o>>1)&3)) << 4);
                    uint32_t ah[4];
                    ldsm4(ah, ad);
                    #pragma unroll
                    for (int np = 0; np < 2; np++)
                        #pragma unroll
                        for (int hf = 0; hf < 2; hf++) {
                            int nt = np*2 + hf;
                            mma_h(acc[mt][nt], ah, bh[np][hf*2], bh[np][hf*2+1]);
                            mma_h(acc[mt][nt], ah, bl[np][hf*2], bl[np][hf*2+1]);
                        }
                }
            }
        }

        // ---- finish gather: interp + pack + STS for s chunk q+1 ----
        if (more) {
            uint32_t sdst = ((q+1) & 1) ? SH1 : SH0;
            uint4 hv, lv;
            uint32_t* hp = &hv.x; uint32_t* lp = &lv.x;
            {
                float r0 = (C0[0].x*w00 + C0[1].x*w01 + C0[2].x*w10 + C0[3].x*w11) * mmv;
                float r1 = (C0[0].y*w00 + C0[1].y*w01 + C0[2].y*w10 + C0[3].y*w11) * mmv;
                float r2 = (C0[0].z*w00 + C0[1].z*w01 + C0[2].z*w10 + C0[3].z*w11) * mmv;
                float r3 = (C0[0].w*w00 + C0[1].w*w01 + C0[2].w*w10 + C0[3].w*w11) * mmv;
                hp[0] = pack_h_hi(r0, r1); hp[1] = pack_h_hi(r2, r3);
                lp[0] = pack_h_lo(r0, r1); lp[1] = pack_h_lo(r2, r3);
            }
            {
                float r0 = (C1[0].x*w00 + C1[1].x*w01 + C1[2].x*w10 + C1[3].x*w11) * mmv;
                float r1 = (C1[0].y*w00 + C1[1].y*w01 + C1[2].y*w10 + C1[3].y*w11) * mmv;
                float r2 = (C1[0].z*w00 + C1[1].z*w01 + C1[2].z*w10 + C1[3].z*w11) * mmv;
                float r3 = (C1[0].w*w00 + C1[1].w*w01 + C1[2].w*w10 + C1[3].w*w11) * mmv;
                hp[2] = pack_h_hi(r0, r1); hp[3] = pack_h_hi(r2, r3);
                lp[2] = pack_h_lo(r0, r1); lp[3] = pack_h_lo(r2, r3);
            }
            *(uint4*)(smc + sdst + s_off) = hv;
            *(uint4*)(smc + sdst + 4096u + s_off) = lv;
        }

        __syncthreads();
    }

    // ---- epilogue: BN + ReLU ----
    int tg = lane & 3, g = lane >> 2;
    #pragma unroll
    for (int mt = 0; mt < 4; mt++) {
        int o0 = ob + mt*16 + g;
        int o1 = o0 + 8;
        float A0 = g_bnA[o0], B0 = g_bnB[o0];
        float A1 = g_bnA[o1], B1 = g_bnB[o1];
        float* r0 = out + ((size_t)(b*On + o0))*HWn + hwb;
        float* r1 = out + ((size_t)(b*On + o1))*HWn + hwb;
        #pragma unroll
        for (int nt = 0; nt < 4; nt++) {
            int p0 = pb + nt*8 + tg*2;
            float2 v0, v1;
            v0.x = fmaxf(acc[mt][nt][0]*A0 + B0, 0.f);
            v0.y = fmaxf(acc[mt][nt][1]*A0 + B0, 0.f);
            v1.x = fmaxf(acc[mt][nt][2]*A1 + B1, 0.f);
            v1.y = fmaxf(acc[mt][nt][3]*A1 + B1, 0.f);
            *(float2*)(r0 + p0) = v0;
            *(float2*)(r1 + p0) = v1;
        }
    }
}

// ---------------- launch ----------------
extern "C" void kernel_launch(void* const* d_in, const int* in_sizes, int n_in,
                              void* d_out, int out_size) {
    const float* x      = (const float*)d_in[0];
    const float* w_off  = (const float*)d_in[1];
    const float* b_off  = (const float*)d_in[2];
    const float* w_dcn  = (const float*)d_in[3];
    const float* b_dcn  = (const float*)d_in[4];
    const float* gamma  = (const float*)d_in[5];
    const float* beta   = (const float*)d_in[6];
    const float* rmean  = (const float*)d_in[7];
    const float* rvar   = (const float*)d_in[8];
    float* out = (float*)d_out;

    cudaFuncSetAttribute(main_kernel, cudaFuncAttributeMaxDynamicSharedMemorySize, SMEM_BYTES);
    cudaFuncSetAttribute(main_kernel, cudaFuncAttributePreferredSharedMemoryCarveout, 100);
    cudaFuncSetAttribute(offset_mma_kernel, cudaFuncAttributeMaxDynamicSharedMemorySize, OSMEM);

    prep_kernel<<<256, 256>>>(w_off, w_dcn, b_dcn, gamma, beta, rmean, rvar);

    dim3 tgrid(Wn/32, Cn/32, Bn*Hn);
    transpose_kernel<<<tgrid, dim3(32, 8)>>>(x);

    offset_mma_kernel<<<(Bn*HWn)/OTP, ONT, OSMEM>>>(b_off);

    main_kernel<<<(Bn*HWn)/TPIX, NT, SMEM_BYTES>>>(out);
}

// round 13
// speedup vs baseline: 4.3637x; 1.3442x over previous
#include <cuda_runtime.h>
#include <cuda_fp16.h>
#include <cstdint>

typedef unsigned long long ull;

#define KKn  9
#define Bn   8
#define Cn   256
#define Hn   96
#define Wn   96
#define On   256
#define HWn  (Hn*Wn)          // 9216
#define KDIM (Cn*KKn)         // 2304

// ---- main mma kernel ----
#define NT    256
#define TPIX  64              // pixels per CTA
#define NCH   72              // K chunks of 32
#define NCOORD (TPIX*KKn)     // 576

// main smem byte offsets (fp16 1-pass: w hi; s hi only)
#define WH0   0u              // [256][32] fp16 = 16384
#define WH1   16384u
#define SH0   32768u          // [64][32] fp16 = 4096
#define SH1   36864u
#define CO_B  40960u
#define SMEM_BYTES (40960 + 3*NCOORD*4)   // 47872 -> 2 blocks/SM

// ---- offset mma kernel (2-pass fp16, unchanged) ----
#define ONT   128
#define OTP   128             // pixels per CTA
#define OAH0  0u              // [32][32] fp16 = 2048
#define OAH1  2048u
#define OBH0  4096u           // [128][32] fp16 = 8192
#define OBL0  12288u
#define OBH1  20480u
#define OBL1  28672u
#define OV_B  36864u
#define OVSTR 132
#define OSMEM (36864 + 28*OVSTR*4)        // 51648

// ---------------- scratch ----------------
__device__ float g_xt[Bn*HWn*Cn];        // x transposed to NHWC
__device__ float g_py [Bn*KKn*HWn];
__device__ float g_px [Bn*KKn*HWn];
__device__ float g_msk[Bn*KKn*HWn];
__device__ __half g_wh [On*KDIM];        // main w fp16 [o][kk*256+c]
__device__ __half g_woh[32*KDIM];        // offset w fp16 [o pad32][kk*256+c]
__device__ float g_bnA[On];
__device__ float g_bnB[On];

// ---------------- helpers ----------------
__device__ __forceinline__ uint32_t smem_u32(const void* p) {
    return (uint32_t)__cvta_generic_to_shared(p);
}
__device__ __forceinline__ void cp16(uint32_t dst, const void* src) {
    asm volatile("cp.async.cg.shared.global [%0], [%1], 16;" :: "r"(dst), "l"(src));
}
#define CP_COMMIT()  asm volatile("cp.async.commit_group;")
#define CP_WAIT(n)   asm volatile("cp.async.wait_group %0;" :: "n"(n))

__device__ __forceinline__ void ldsm4(uint32_t* r, uint32_t addr) {
    asm volatile("ldmatrix.sync.aligned.m8n8.x4.shared.b16 {%0,%1,%2,%3}, [%4];"
        : "=r"(r[0]), "=r"(r[1]), "=r"(r[2]), "=r"(r[3]) : "r"(addr));
}
__device__ __forceinline__ void mma_h(float* d, const uint32_t* a, uint32_t b0, uint32_t b1) {
    asm volatile("mma.sync.aligned.m16n8k16.row.col.f32.f16.f16.f32 "
        "{%0,%1,%2,%3}, {%4,%5,%6,%7}, {%8,%9}, {%0,%1,%2,%3};"
        : "+f"(d[0]), "+f"(d[1]), "+f"(d[2]), "+f"(d[3])
        : "r"(a[0]), "r"(a[1]), "r"(a[2]), "r"(a[3]), "r"(b0), "r"(b1));
}
__device__ __forceinline__ uint32_t pack_h_hi(float a, float b) {
    __half2 h = __floats2half2_rn(a, b);
    return *(uint32_t*)&h;
}
__device__ __forceinline__ uint32_t pack_h_lo(float a, float b) {
    float ra = a - __half2float(__float2half_rn(a));
    float rb = b - __half2float(__float2half_rn(b));
    __half2 h = __floats2half2_rn(ra, rb);
    return *(uint32_t*)&h;
}

// ---------------- prep ----------------
__global__ void prep_kernel(const float* __restrict__ w_off,
                            const float* __restrict__ w_dcn,
                            const float* __restrict__ b_dcn,
                            const float* __restrict__ gamma,
                            const float* __restrict__ beta,
                            const float* __restrict__ rmean,
                            const float* __restrict__ rvar) {
    int t = blockIdx.x * blockDim.x + threadIdx.x;
    int stride = gridDim.x * blockDim.x;
    for (int i = t; i < On*KDIM; i += stride) {
        int K = i % KDIM; int o = i / KDIM;
        int kk = K / Cn;  int c = K % Cn;
        g_wh[i] = __float2half_rn(w_dcn[(o*Cn + c)*KKn + kk]);
    }
    for (int i = t; i < 32*KDIM; i += stride) {
        int K = i % KDIM; int o = i / KDIM;
        int kk = K / Cn;  int c = K % Cn;
        float v = (o < 27) ? w_off[(o*Cn + c)*KKn + kk] : 0.f;
        g_woh[i] = __float2half_rn(v);
    }
    if (t < On) {
        float inv = rsqrtf(rvar[t] + 1e-5f);
        float A = gamma[t] * inv;
        g_bnA[t] = A;
        g_bnB[t] = (b_dcn[t] - rmean[t]) * A + beta[t];
    }
}

// ---------------- NCHW -> NHWC transpose ----------------
__global__ void transpose_kernel(const float* __restrict__ x) {
    __shared__ float tile[32][33];
    int bh = blockIdx.z;
    int c0 = blockIdx.y * 32;
    int w0 = blockIdx.x * 32;
    int b = bh / Hn; int h = bh % Hn;
    for (int i = threadIdx.y; i < 32; i += 8)
        tile[i][threadIdx.x] = x[((b*Cn + c0 + i)*Hn + h)*Wn + w0 + threadIdx.x];
    __syncthreads();
    for (int i = threadIdx.y; i < 32; i += 8)
        g_xt[((size_t)(b*Hn + h)*Wn + w0 + i)*Cn + c0 + threadIdx.x] = tile[threadIdx.x][i];
}

// ---------------- offset conv via fp16 2-pass mma ----------------
__global__ __launch_bounds__(ONT) void offset_mma_kernel(const float* __restrict__ b_off) {
    extern __shared__ char smc[];
    uint32_t sb = smem_u32(smc);
    float* ov = (float*)(smc + OV_B);

    int tid  = threadIdx.x;
    int lane = tid & 31;
    int wid  = tid >> 5;
    int pixb = blockIdx.x * OTP;
    int b    = pixb / HWn;
    int hwb  = pixb % HWn;
    const float* xtb = g_xt + (size_t)b * (HWn*Cn);

    auto fillB = [&](int q, uint32_t bh_off, uint32_t bl_off) {
        int kk = q >> 3;
        int c32 = (q & 7) * 32;
        int dy = kk/3 - 1, dx = kk%3 - 1;
        #pragma unroll
        for (int i = 0; i < 4; i++) {
            int t = i*ONT + tid;
            int p = t >> 2, quad = t & 3;
            int hw = hwb + p;
            int h = hw / Wn, w = hw % Wn;
            int y = h + dy, x = w + dx;
            float4 va = make_float4(0.f,0.f,0.f,0.f), vb = va;
            if ((unsigned)y < (unsigned)Hn && (unsigned)x < (unsigned)Wn) {
                const float* r = xtb + ((y*Wn + x) << 8) + c32 + quad*8;
                va = *(const float4*)r;
                vb = *(const float4*)(r + 4);
            }
            uint4 hv, lv;
            hv.x = pack_h_hi(va.x, va.y); hv.y = pack_h_hi(va.z, va.w);
            hv.z = pack_h_hi(vb.x, vb.y); hv.w = pack_h_hi(vb.z, vb.w);
            lv.x = pack_h_lo(va.x, va.y); lv.y = pack_h_lo(va.z, va.w);
            lv.z = pack_h_lo(vb.x, vb.y); lv.w = pack_h_lo(vb.z, vb.w);
            uint32_t off = (uint32_t)p*64u + (uint32_t)((quad ^ ((p>>1)&3)) << 4);
            *(uint4*)(smc + bh_off + off) = hv;
            *(uint4*)(smc + bl_off + off) = lv;
        }
    };
    auto cpA = [&](int q, uint32_t ah_off) {
        int row = tid >> 2;
        int quad = tid & 3;
        const __half* src = g_woh + (size_t)row*KDIM + q*32 + quad*8;
        uint32_t dst = sb + ah_off + (uint32_t)row*64u
                     + (uint32_t)((quad ^ ((row>>1)&3)) << 4);
        cp16(dst, src);
        CP_COMMIT();
    };

    cpA(0, OAH0);
    fillB(0, OBH0, OBL0);

    int pb = wid * 32;
    float acc[2][4][4];
    #pragma unroll
    for (int mt = 0; mt < 2; mt++)
        #pragma unroll
        for (int nt = 0; nt < 4; nt++)
            #pragma unroll
            for (int e = 0; e < 4; e++) acc[mt][nt][e] = 0.f;

    #pragma unroll 1
    for (int q = 0; q < NCH; q++) {
        int buf = q & 1;
        bool more = (q + 1 < NCH);
        if (more) cpA(q+1, (q+1)&1 ? OAH1 : OAH0);
        if (more) { CP_WAIT(1); } else { CP_WAIT(0); }
        __syncthreads();

        uint32_t ab = sb + (buf ? OAH1 : OAH0);
        uint32_t bb = sb + (buf ? OBH1 : OBH0);
        #pragma unroll
        for (int ks = 0; ks < 2; ks++) {
            uint32_t bh[2][4], bl[2][4];
            #pragma unroll
            for (int np = 0; np < 2; np++) {
                int p = pb + np*16 + (lane & 7) + ((lane >> 4) << 3);
                int u = ks*2 + ((lane >> 3) & 1);
                uint32_t bd = bb + (uint32_t)p*64u + (uint32_t)((u ^ ((p>>1)&3)) << 4);
                ldsm4(bh[np], bd);
                ldsm4(bl[np], bd + 8192u);
            }
            #pragma unroll
            for (int mt = 0; mt < 2; mt++) {
                int o = mt*16 + (lane & 15);
                int u = ks*2 + (lane >> 4);
                uint32_t ad = ab + (uint32_t)o*64u + (uint32_t)((u ^ ((o>>1)&3)) << 4);
                uint32_t ah[4];
                ldsm4(ah, ad);
                #pragma unroll
                for (int np = 0; np < 2; np++)
                    #pragma unroll
                    for (int hf = 0; hf < 2; hf++) {
                        int nt = np*2 + hf;
                        mma_h(acc[mt][nt], ah, bh[np][hf*2], bh[np][hf*2+1]);
                        mma_h(acc[mt][nt], ah, bl[np][hf*2], bl[np][hf*2+1]);
                    }
            }
        }

        if (more) fillB(q+1, (q+1)&1 ? OBH1 : OBH0, (q+1)&1 ? OBL1 : OBL0);
        __syncthreads();
    }

    // ---- write acc to ov ----
    #pragma unroll
    for (int mt = 0; mt < 2; mt++) {
        int o0 = mt*16 + (lane >> 2);
        int o1 = o0 + 8;
        #pragma unroll
        for (int nt = 0; nt < 4; nt++) {
            int p = pb + nt*8 + (lane & 3)*2;
            if (o0 < 27) {
                ov[o0*OVSTR + p]   = acc[mt][nt][0];
                ov[o0*OVSTR + p+1] = acc[mt][nt][1];
            }
            if (o1 < 27) {
                ov[o1*OVSTR + p]   = acc[mt][nt][2];
                ov[o1*OVSTR + p+1] = acc[mt][nt][3];
            }
        }
    }
    __syncthreads();

    // ---- epilogue: py/px/mask ----
    {
        int p = tid;
        int hw = hwb + p;
        int h = hw / Wn, w = hw % Wn;
        #pragma unroll
        for (int k = 0; k < KKn; k++) {
            float py = ov[(2*k)*OVSTR + p]   + b_off[2*k]   + (float)(h + k/3 - 1);
            float px = ov[(2*k+1)*OVSTR + p] + b_off[2*k+1] + (float)(w + k%3 - 1);
            float mv = ov[(18+k)*OVSTR + p]  + b_off[18+k];
            float mm = 1.f / (1.f + expf(-mv));
            int idx = (b*KKn + k)*HWn + hw;
            g_py[idx] = py; g_px[idx] = px; g_msk[idx] = mm;
        }
    }
}

// ---------------- main: fp16 1-pass mma fused DCN ----------------
__device__ __forceinline__ float4 corner_ld(const float* __restrict__ xtb, int y, int x, int c4) {
    if ((unsigned)y < (unsigned)Hn && (unsigned)x < (unsigned)Wn)
        return *(const float4*)(xtb + ((y*Wn + x) << 8) + (c4 << 2));
    return make_float4(0.f, 0.f, 0.f, 0.f);
}

__global__ __launch_bounds__(NT, 2) void main_kernel(float* __restrict__ out) {
    extern __shared__ char smc[];
    uint32_t sb = smem_u32(smc);
    float* spy = (float*)(smc + CO_B);
    float* spx = spy + NCOORD;
    float* smk = spx + NCOORD;

    int tid  = threadIdx.x;
    int lane = tid & 31;
    int wid  = tid >> 5;
    int pixb = blockIdx.x * TPIX;
    int b    = pixb / HWn;
    int hwb  = pixb % HWn;

    for (int i = tid; i < NCOORD; i += NT) {
        int p = i / KKn, k = i % KKn;
        int gi = (b*KKn + k)*HWn + hwb + p;
        spy[i] = g_py[gi]; spx[i] = g_px[gi]; smk[i] = g_msk[gi];
    }
    __syncthreads();

    const float* xtb = g_xt + (size_t)b * (HWn*Cn);

    int gp  = tid >> 2;
    int gcq = tid & 3;
    uint32_t s_off = (uint32_t)gp*64u + (uint32_t)((gcq ^ ((gp >> 1) & 3)) << 4);

    auto cpW = [&](int q) {
        uint32_t wb = (q & 1) ? WH1 : WH0;
        #pragma unroll
        for (int i = 0; i < 4; i++) {
            int id = i*NT + tid;
            int o = id >> 2;
            int u = id & 3;
            const __half* src = g_wh + (size_t)o*KDIM + q*32 + u*8;
            uint32_t dst = sb + wb + (uint32_t)o*64u
                         + (uint32_t)((u ^ ((o>>1)&3)) << 4);
            cp16(dst, src);
        }
        CP_COMMIT();
    };

    // full gather of s chunk 0 (prologue)
    {
        cpW(0);
        int c4b = gcq*2;
        float py = spy[gp*KKn], px = spx[gp*KKn], mm = smk[gp*KKn];
        float fy = floorf(py), fx = floorf(px);
        int y0 = (int)fy, x0 = (int)fx;
        float wy = py - fy, wx = px - fx;
        float w00 = (1.f-wy)*(1.f-wx), w01 = (1.f-wy)*wx;
        float w10 = wy*(1.f-wx),       w11 = wy*wx;
        uint4 hv;
        uint32_t* hp = &hv.x;
        #pragma unroll
        for (int g = 0; g < 2; g++) {
            int c4 = c4b + g;
            float4 v00 = corner_ld(xtb, y0,   x0,   c4);
            float4 v01 = corner_ld(xtb, y0,   x0+1, c4);
            float4 v10 = corner_ld(xtb, y0+1, x0,   c4);
            float4 v11 = corner_ld(xtb, y0+1, x0+1, c4);
            float r0 = (v00.x*w00 + v01.x*w01 + v10.x*w10 + v11.x*w11) * mm;
            float r1 = (v00.y*w00 + v01.y*w01 + v10.y*w10 + v11.y*w11) * mm;
            float r2 = (v00.z*w00 + v01.z*w01 + v10.z*w10 + v11.z*w11) * mm;
            float r3 = (v00.w*w00 + v01.w*w01 + v10.w*w10 + v11.w*w11) * mm;
            hp[g*2]   = pack_h_hi(r0, r1);
            hp[g*2+1] = pack_h_hi(r2, r3);
        }
        *(uint4*)(smc + SH0 + s_off) = hv;
    }

    int ob = (wid >> 1) * 64;
    int pb = (wid & 1) * 32;
    float acc[4][4][4];
    #pragma unroll
    for (int mt = 0; mt < 4; mt++)
        #pragma unroll
        for (int nt = 0; nt < 4; nt++)
            #pragma unroll
            for (int e = 0; e < 4; e++) acc[mt][nt][e] = 0.f;

    #pragma unroll 1
    for (int q = 0; q < NCH; q++) {
        int buf = q & 1;
        bool more = (q + 1 < NCH);

        if (more) cpW(q+1);

        // ---- pre-issue corner LDGs for s chunk q+1 (covered by MMA below) ----
        float4 C0[4], C1[4];
        float w00, w01, w10, w11, mmv;
        if (more) {
            int qn = q + 1;
            int kk = qn >> 3;
            int c4b = ((qn & 7) << 3) + gcq*2;
            float py = spy[gp*KKn + kk], px = spx[gp*KKn + kk];
            mmv = smk[gp*KKn + kk];
            float fy = floorf(py), fx = floorf(px);
            int y0 = (int)fy, x0 = (int)fx;
            float wy = py - fy, wx = px - fx;
            w00 = (1.f-wy)*(1.f-wx); w01 = (1.f-wy)*wx;
            w10 = wy*(1.f-wx);       w11 = wy*wx;
            C0[0] = corner_ld(xtb, y0,   x0,   c4b);
            C0[1] = corner_ld(xtb, y0,   x0+1, c4b);
            C0[2] = corner_ld(xtb, y0+1, x0,   c4b);
            C0[3] = corner_ld(xtb, y0+1, x0+1, c4b);
            C1[0] = corner_ld(xtb, y0,   x0,   c4b+1);
            C1[1] = corner_ld(xtb, y0,   x0+1, c4b+1);
            C1[2] = corner_ld(xtb, y0+1, x0,   c4b+1);
            C1[3] = corner_ld(xtb, y0+1, x0+1, c4b+1);
        }

        if (more) { CP_WAIT(1); } else { CP_WAIT(0); }
        __syncthreads();

        // ---- MMA on chunk q (1-pass) ----
        {
            uint32_t whb = sb + (buf ? WH1 : WH0);
            uint32_t shb = sb + (buf ? SH1 : SH0);
            #pragma unroll
            for (int ks = 0; ks < 2; ks++) {
                uint32_t bh[2][4];
                #pragma unroll
                for (int np = 0; np < 2; np++) {
                    int p = pb + np*16 + (lane & 7) + ((lane >> 4) << 3);
                    int u = ks*2 + ((lane >> 3) & 1);
                    uint32_t bd = shb + (uint32_t)p*64u + (uint32_t)((u ^ ((p>>1)&3)) << 4);
                    ldsm4(bh[np], bd);
                }
                #pragma unroll
                for (int mt = 0; mt < 4; mt++) {
                    int o = ob + mt*16 + (lane & 15);
                    int u = ks*2 + (lane >> 4);
                    uint32_t ad = whb + (uint32_t)o*64u + (uint32_t)((u ^ ((o>>1)&3)) << 4);
                    uint32_t ah[4];
                    ldsm4(ah, ad);
                    #pragma unroll
                    for (int np = 0; np < 2; np++)
                        #pragma unroll
                        for (int hf = 0; hf < 2; hf++) {
                            int nt = np*2 + hf;
                            mma_h(acc[mt][nt], ah, bh[np][hf*2], bh[np][hf*2+1]);
                        }
                }
            }
        }

        // ---- finish gather: interp + pack + STS for s chunk q+1 ----
        if (more) {
            uint32_t sdst = ((q+1) & 1) ? SH1 : SH0;
            uint4 hv;
            uint32_t* hp = &hv.x;
            {
                float r0 = (C0[0].x*w00 + C0[1].x*w01 + C0[2].x*w10 + C0[3].x*w11) * mmv;
                float r1 = (C0[0].y*w00 + C0[1].y*w01 + C0[2].y*w10 + C0[3].y*w11) * mmv;
                float r2 = (C0[0].z*w00 + C0[1].z*w01 + C0[2].z*w10 + C0[3].z*w11) * mmv;
                float r3 = (C0[0].w*w00 + C0[1].w*w01 + C0[2].w*w10 + C0[3].w*w11) * mmv;
                hp[0] = pack_h_hi(r0, r1); hp[1] = pack_h_hi(r2, r3);
            }
            {
                float r0 = (C1[0].x*w00 + C1[1].x*w01 + C1[2].x*w10 + C1[3].x*w11) * mmv;
                float r1 = (C1[0].y*w00 + C1[1].y*w01 + C1[2].y*w10 + C1[3].y*w11) * mmv;
                float r2 = (C1[0].z*w00 + C1[1].z*w01 + C1[2].z*w10 + C1[3].z*w11) * mmv;
                float r3 = (C1[0].w*w00 + C1[1].w*w01 + C1[2].w*w10 + C1[3].w*w11) * mmv;
                hp[2] = pack_h_hi(r0, r1); hp[3] = pack_h_hi(r2, r3);
            }
            *(uint4*)(smc + sdst + s_off) = hv;
        }

        __syncthreads();
    }

    // ---- epilogue: BN + ReLU ----
    int tg = lane & 3, g = lane >> 2;
    #pragma unroll
    for (int mt = 0; mt < 4; mt++) {
        int o0 = ob + mt*16 + g;
        int o1 = o0 + 8;
        float A0 = g_bnA[o0], B0 = g_bnB[o0];
        float A1 = g_bnA[o1], B1 = g_bnB[o1];
        float* r0 = out + ((size_t)(b*On + o0))*HWn + hwb;
        float* r1 = out + ((size_t)(b*On + o1))*HWn + hwb;
        #pragma unroll
        for (int nt = 0; nt < 4; nt++) {
            int p0 = pb + nt*8 + tg*2;
            float2 v0, v1;
            v0.x = fmaxf(acc[mt][nt][0]*A0 + B0, 0.f);
            v0.y = fmaxf(acc[mt][nt][1]*A0 + B0, 0.f);
            v1.x = fmaxf(acc[mt][nt][2]*A1 + B1, 0.f);
            v1.y = fmaxf(acc[mt][nt][3]*A1 + B1, 0.f);
            *(float2*)(r0 + p0) = v0;
            *(float2*)(r1 + p0) = v1;
        }
    }
}

// ---------------- launch ----------------
extern "C" void kernel_launch(void* const* d_in, const int* in_sizes, int n_in,
                              void* d_out, int out_size) {
    const float* x      = (const float*)d_in[0];
    const float* w_off  = (const float*)d_in[1];
    const float* b_off  = (const float*)d_in[2];
    const float* w_dcn  = (const float*)d_in[3];
    const float* b_dcn  = (const float*)d_in[4];
    const float* gamma  = (const float*)d_in[5];
    const float* beta   = (const float*)d_in[6];
    const float* rmean  = (const float*)d_in[7];
    const float* rvar   = (const float*)d_in[8];
    float* out = (float*)d_out;

    cudaFuncSetAttribute(main_kernel, cudaFuncAttributeMaxDynamicSharedMemorySize, SMEM_BYTES);
    cudaFuncSetAttribute(main_kernel, cudaFuncAttributePreferredSharedMemoryCarveout, 100);
    cudaFuncSetAttribute(offset_mma_kernel, cudaFuncAttributeMaxDynamicSharedMemorySize, OSMEM);

    prep_kernel<<<256, 256>>>(w_off, w_dcn, b_dcn, gamma, beta, rmean, rvar);

    dim3 tgrid(Wn/32, Cn/32, Bn*Hn);
    transpose_kernel<<<tgrid, dim3(32, 8)>>>(x);

    offset_mma_kernel<<<(Bn*HWn)/OTP, ONT, OSMEM>>>(b_off);

    main_kernel<<<(Bn*HWn)/TPIX, NT, SMEM_BYTES>>>(out);
}

// round 14
// speedup vs baseline: 5.8639x; 1.3438x over previous
#include <cuda_runtime.h>
#include <cuda_fp16.h>
#include <cstdint>

typedef unsigned long long ull;

#define KKn  9
#define Bn   8
#define Cn   256
#define Hn   96
#define Wn   96
#define On   256
#define HWn  (Hn*Wn)          // 9216
#define KDIM (Cn*KKn)         // 2304

// ---- main mma kernel ----
#define NT    256
#define TPIX  64              // pixels per CTA
#define NCH   72              // K chunks of 32
#define NCOORD (TPIX*KKn)     // 576

// main smem byte offsets (fp16 1-pass: w hi; s hi only)
#define WH0   0u              // [256][32] fp16 = 16384
#define WH1   16384u
#define SH0   32768u          // [64][32] fp16 = 4096
#define SH1   36864u
#define CO_B  40960u
#define SMEM_BYTES (40960 + 3*NCOORD*4)   // 47872 -> 2 blocks/SM

// ---- offset mma kernel (1-pass fp16) ----
#define ONT   128
#define OTP   128             // pixels per CTA
#define OAH0  0u              // [32][32] fp16 = 2048
#define OAH1  2048u
#define OBH0  4096u           // [128][32] fp16 = 8192
#define OBH1  12288u
#define OV_B  20480u
#define OVSTR 132
#define OSMEM (20480 + 28*OVSTR*4)        // 35264

// ---------------- scratch ----------------
__device__ __half g_xth[Bn*HWn*Cn];      // x transposed to NHWC, fp16
__device__ float g_py [Bn*KKn*HWn];
__device__ float g_px [Bn*KKn*HWn];
__device__ float g_msk[Bn*KKn*HWn];
__device__ __half g_wh [On*KDIM];        // main w fp16 [o][kk*256+c]
__device__ __half g_woh[32*KDIM];        // offset w fp16 [o pad32][kk*256+c]
__device__ float g_bnA[On];
__device__ float g_bnB[On];

// ---------------- helpers ----------------
__device__ __forceinline__ uint32_t smem_u32(const void* p) {
    return (uint32_t)__cvta_generic_to_shared(p);
}
__device__ __forceinline__ void cp16(uint32_t dst, const void* src) {
    asm volatile("cp.async.cg.shared.global [%0], [%1], 16;" :: "r"(dst), "l"(src));
}
__device__ __forceinline__ void cp16z(uint32_t dst, const void* src, uint32_t sz) {
    asm volatile("cp.async.cg.shared.global [%0], [%1], 16, %2;"
        :: "r"(dst), "l"(src), "r"(sz));
}
#define CP_COMMIT()  asm volatile("cp.async.commit_group;")
#define CP_WAIT(n)   asm volatile("cp.async.wait_group %0;" :: "n"(n))

__device__ __forceinline__ void ldsm4(uint32_t* r, uint32_t addr) {
    asm volatile("ldmatrix.sync.aligned.m8n8.x4.shared.b16 {%0,%1,%2,%3}, [%4];"
        : "=r"(r[0]), "=r"(r[1]), "=r"(r[2]), "=r"(r[3]) : "r"(addr));
}
__device__ __forceinline__ void mma_h(float* d, const uint32_t* a, uint32_t b0, uint32_t b1) {
    asm volatile("mma.sync.aligned.m16n8k16.row.col.f32.f16.f16.f32 "
        "{%0,%1,%2,%3}, {%4,%5,%6,%7}, {%8,%9}, {%0,%1,%2,%3};"
        : "+f"(d[0]), "+f"(d[1]), "+f"(d[2]), "+f"(d[3])
        : "r"(a[0]), "r"(a[1]), "r"(a[2]), "r"(a[3]), "r"(b0), "r"(b1));
}

// ---------------- prep ----------------
__global__ void prep_kernel(const float* __restrict__ w_off,
                            const float* __restrict__ w_dcn,
                            const float* __restrict__ b_dcn,
                            const float* __restrict__ gamma,
                            const float* __restrict__ beta,
                            const float* __restrict__ rmean,
                            const float* __restrict__ rvar) {
    int t = blockIdx.x * blockDim.x + threadIdx.x;
    int stride = gridDim.x * blockDim.x;
    for (int i = t; i < On*KDIM; i += stride) {
        int K = i % KDIM; int o = i / KDIM;
        int kk = K / Cn;  int c = K % Cn;
        g_wh[i] = __float2half_rn(w_dcn[(o*Cn + c)*KKn + kk]);
    }
    for (int i = t; i < 32*KDIM; i += stride) {
        int K = i % KDIM; int o = i / KDIM;
        int kk = K / Cn;  int c = K % Cn;
        float v = (o < 27) ? w_off[(o*Cn + c)*KKn + kk] : 0.f;
        g_woh[i] = __float2half_rn(v);
    }
    if (t < On) {
        float inv = rsqrtf(rvar[t] + 1e-5f);
        float A = gamma[t] * inv;
        g_bnA[t] = A;
        g_bnB[t] = (b_dcn[t] - rmean[t]) * A + beta[t];
    }
}

// ---------------- NCHW fp32 -> NHWC fp16 transpose ----------------
__global__ void transpose_kernel(const float* __restrict__ x) {
    __shared__ float tile[32][33];
    int bh = blockIdx.z;
    int c0 = blockIdx.y * 32;
    int w0 = blockIdx.x * 32;
    int b = bh / Hn; int h = bh % Hn;
    for (int i = threadIdx.y; i < 32; i += 8)
        tile[i][threadIdx.x] = x[((b*Cn + c0 + i)*Hn + h)*Wn + w0 + threadIdx.x];
    __syncthreads();
    for (int i = threadIdx.y; i < 32; i += 8)
        g_xth[((size_t)(b*Hn + h)*Wn + w0 + i)*Cn + c0 + threadIdx.x] =
            __float2half_rn(tile[threadIdx.x][i]);
}

// ---------------- offset conv via fp16 1-pass mma ----------------
__global__ __launch_bounds__(ONT) void offset_mma_kernel(const float* __restrict__ b_off) {
    extern __shared__ char smc[];
    uint32_t sb = smem_u32(smc);
    float* ov = (float*)(smc + OV_B);

    int tid  = threadIdx.x;
    int lane = tid & 31;
    int wid  = tid >> 5;
    int pixb = blockIdx.x * OTP;
    int b    = pixb / HWn;
    int hwb  = pixb % HWn;
    const __half* xtbh = g_xth + (size_t)b * (HWn*Cn);

    // stage chunk q: A weights + B tile, all via cp.async (zfill for OOB)
    auto stage = [&](int q) {
        uint32_t ab = (q & 1) ? OAH1 : OAH0;
        uint32_t bb = (q & 1) ? OBH1 : OBH0;
        {
            int row = tid >> 2, quad = tid & 3;
            cp16(sb + ab + (uint32_t)row*64u + (uint32_t)((quad ^ ((row>>1)&3)) << 4),
                 g_woh + (size_t)row*KDIM + q*32 + quad*8);
        }
        int kk = q >> 3;
        int c32 = (q & 7) * 32;
        int dy = kk/3 - 1, dx = kk%3 - 1;
        #pragma unroll
        for (int i = 0; i < 4; i++) {
            int t = i*ONT + tid;
            int p = t >> 2, quad = t & 3;
            int hw = hwb + p;
            int h = hw / Wn, w = hw % Wn;
            int y = h + dy, x = w + dx;
            bool ok = ((unsigned)y < (unsigned)Hn) && ((unsigned)x < (unsigned)Wn);
            const __half* src = ok ? (xtbh + (((y*Wn + x) << 8) + c32 + quad*8)) : xtbh;
            uint32_t dst = sb + bb + (uint32_t)p*64u + (uint32_t)((quad ^ ((p>>1)&3)) << 4);
            cp16z(dst, src, ok ? 16u : 0u);
        }
        CP_COMMIT();
    };

    stage(0);

    int pb = wid * 32;
    float acc[2][4][4];
    #pragma unroll
    for (int mt = 0; mt < 2; mt++)
        #pragma unroll
        for (int nt = 0; nt < 4; nt++)
            #pragma unroll
            for (int e = 0; e < 4; e++) acc[mt][nt][e] = 0.f;

    #pragma unroll 1
    for (int q = 0; q < NCH; q++) {
        int buf = q & 1;
        bool more = (q + 1 < NCH);
        if (more) stage(q+1);
        if (more) { CP_WAIT(1); } else { CP_WAIT(0); }
        __syncthreads();

        uint32_t ab = sb + (buf ? OAH1 : OAH0);
        uint32_t bb = sb + (buf ? OBH1 : OBH0);
        #pragma unroll
        for (int ks = 0; ks < 2; ks++) {
            uint32_t bh[2][4];
            #pragma unroll
            for (int np = 0; np < 2; np++) {
                int p = pb + np*16 + (lane & 7) + ((lane >> 4) << 3);
                int u = ks*2 + ((lane >> 3) & 1);
                uint32_t bd = bb + (uint32_t)p*64u + (uint32_t)((u ^ ((p>>1)&3)) << 4);
                ldsm4(bh[np], bd);
            }
            #pragma unroll
            for (int mt = 0; mt < 2; mt++) {
                int o = mt*16 + (lane & 15);
                int u = ks*2 + (lane >> 4);
                uint32_t ad = ab + (uint32_t)o*64u + (uint32_t)((u ^ ((o>>1)&3)) << 4);
                uint32_t ah[4];
                ldsm4(ah, ad);
                #pragma unroll
                for (int np = 0; np < 2; np++)
                    #pragma unroll
                    for (int hf = 0; hf < 2; hf++)
                        mma_h(acc[mt][np*2+hf], ah, bh[np][hf*2], bh[np][hf*2+1]);
            }
        }
        __syncthreads();
    }

    // ---- write acc to ov ----
    #pragma unroll
    for (int mt = 0; mt < 2; mt++) {
        int o0 = mt*16 + (lane >> 2);
        int o1 = o0 + 8;
        #pragma unroll
        for (int nt = 0; nt < 4; nt++) {
            int p = pb + nt*8 + (lane & 3)*2;
            if (o0 < 27) {
                ov[o0*OVSTR + p]   = acc[mt][nt][0];
                ov[o0*OVSTR + p+1] = acc[mt][nt][1];
            }
            if (o1 < 27) {
                ov[o1*OVSTR + p]   = acc[mt][nt][2];
                ov[o1*OVSTR + p+1] = acc[mt][nt][3];
            }
        }
    }
    __syncthreads();

    // ---- epilogue: py/px/mask ----
    {
        int p = tid;
        int hw = hwb + p;
        int h = hw / Wn, w = hw % Wn;
        #pragma unroll
        for (int k = 0; k < KKn; k++) {
            float py = ov[(2*k)*OVSTR + p]   + b_off[2*k]   + (float)(h + k/3 - 1);
            float px = ov[(2*k+1)*OVSTR + p] + b_off[2*k+1] + (float)(w + k%3 - 1);
            float mv = ov[(18+k)*OVSTR + p]  + b_off[18+k];
            float mm = 1.f / (1.f + expf(-mv));
            int idx = (b*KKn + k)*HWn + hw;
            g_py[idx] = py; g_px[idx] = px; g_msk[idx] = mm;
        }
    }
}

// ---------------- main: fp16 1-pass mma fused DCN (fp16 gather) ----------------
__device__ __forceinline__ uint4 corner_ldh(const __half* __restrict__ xtbh, int y, int x, int c) {
    if ((unsigned)y < (unsigned)Hn && (unsigned)x < (unsigned)Wn)
        return *(const uint4*)(xtbh + (((y*Wn + x) << 8) + c));
    return make_uint4(0u, 0u, 0u, 0u);
}

__global__ __launch_bounds__(NT, 2) void main_kernel(float* __restrict__ out) {
    extern __shared__ char smc[];
    uint32_t sb = smem_u32(smc);
    float* spy = (float*)(smc + CO_B);
    float* spx = spy + NCOORD;
    float* smk = spx + NCOORD;

    int tid  = threadIdx.x;
    int lane = tid & 31;
    int wid  = tid >> 5;
    int pixb = blockIdx.x * TPIX;
    int b    = pixb / HWn;
    int hwb  = pixb % HWn;

    for (int i = tid; i < NCOORD; i += NT) {
        int p = i / KKn, k = i % KKn;
        int gi = (b*KKn + k)*HWn + hwb + p;
        spy[i] = g_py[gi]; spx[i] = g_px[gi]; smk[i] = g_msk[gi];
    }
    __syncthreads();

    const __half* xtbh = g_xth + (size_t)b * (HWn*Cn);

    int gp  = tid >> 2;        // pixel 0..63
    int gcq = tid & 3;         // 8-channel (16B) group
    uint32_t s_off = (uint32_t)gp*64u + (uint32_t)((gcq ^ ((gp >> 1) & 3)) << 4);

    auto cpW = [&](int q) {
        uint32_t wb = (q & 1) ? WH1 : WH0;
        #pragma unroll
        for (int i = 0; i < 4; i++) {
            int id = i*NT + tid;
            int o = id >> 2;
            int u = id & 3;
            const __half* src = g_wh + (size_t)o*KDIM + q*32 + u*8;
            uint32_t dst = sb + wb + (uint32_t)o*64u
                         + (uint32_t)((u ^ ((o>>1)&3)) << 4);
            cp16(dst, src);
        }
        CP_COMMIT();
    };

    // half2 bilinear of 4 corner uint4s -> one uint4 of 8 fp16 channels
    auto interp_h2 = [&](uint4 C0, uint4 C1, uint4 C2, uint4 C3,
                         float w00, float w01, float w10, float w11, float mmv) -> uint4 {
        __half2 W00 = __float2half2_rn(w00);
        __half2 W01 = __float2half2_rn(w01);
        __half2 W10 = __float2half2_rn(w10);
        __half2 W11 = __float2half2_rn(w11);
        __half2 MM  = __float2half2_rn(mmv);
        const __half2* c0 = (const __half2*)&C0;
        const __half2* c1 = (const __half2*)&C1;
        const __half2* c2 = (const __half2*)&C2;
        const __half2* c3 = (const __half2*)&C3;
        uint4 res;
        __half2* rp = (__half2*)&res;
        #pragma unroll
        for (int j = 0; j < 4; j++) {
            __half2 a = __hmul2(c0[j], W00);
            a = __hfma2(c1[j], W01, a);
            a = __hfma2(c2[j], W10, a);
            a = __hfma2(c3[j], W11, a);
            rp[j] = __hmul2(a, MM);
        }
        return res;
    };

    // prologue: w chunk 0 + s chunk 0
    {
        cpW(0);
        int c = gcq*8;
        float py = spy[gp*KKn], px = spx[gp*KKn], mm = smk[gp*KKn];
        float fy = floorf(py), fx = floorf(px);
        int y0 = (int)fy, x0 = (int)fx;
        float wy = py - fy, wx = px - fx;
        uint4 C0 = corner_ldh(xtbh, y0,   x0,   c);
        uint4 C1 = corner_ldh(xtbh, y0,   x0+1, c);
        uint4 C2 = corner_ldh(xtbh, y0+1, x0,   c);
        uint4 C3 = corner_ldh(xtbh, y0+1, x0+1, c);
        uint4 r = interp_h2(C0, C1, C2, C3,
                            (1.f-wy)*(1.f-wx), (1.f-wy)*wx, wy*(1.f-wx), wy*wx, mm);
        *(uint4*)(smc + SH0 + s_off) = r;
    }

    int ob = (wid >> 1) * 64;
    int pb = (wid & 1) * 32;
    float acc[4][4][4];
    #pragma unroll
    for (int mt = 0; mt < 4; mt++)
        #pragma unroll
        for (int nt = 0; nt < 4; nt++)
            #pragma unroll
            for (int e = 0; e < 4; e++) acc[mt][nt][e] = 0.f;

    #pragma unroll 1
    for (int q = 0; q < NCH; q++) {
        int buf = q & 1;
        bool more = (q + 1 < NCH);

        if (more) cpW(q+1);

        // ---- pre-issue corner LDGs for s chunk q+1 ----
        uint4 C0, C1, C2, C3;
        float w00, w01, w10, w11, mmv;
        if (more) {
            int qn = q + 1;
            int kk = qn >> 3;
            int c = ((qn & 7) << 5) + gcq*8;
            float py = spy[gp*KKn + kk], px = spx[gp*KKn + kk];
            mmv = smk[gp*KKn + kk];
            float fy = floorf(py), fx = floorf(px);
            int y0 = (int)fy, x0 = (int)fx;
            float wy = py - fy, wx = px - fx;
            w00 = (1.f-wy)*(1.f-wx); w01 = (1.f-wy)*wx;
            w10 = wy*(1.f-wx);       w11 = wy*wx;
            C0 = corner_ldh(xtbh, y0,   x0,   c);
            C1 = corner_ldh(xtbh, y0,   x0+1, c);
            C2 = corner_ldh(xtbh, y0+1, x0,   c);
            C3 = corner_ldh(xtbh, y0+1, x0+1, c);
        }

        if (more) { CP_WAIT(1); } else { CP_WAIT(0); }
        __syncthreads();

        // ---- MMA on chunk q ----
        {
            uint32_t whb = sb + (buf ? WH1 : WH0);
            uint32_t shb = sb + (buf ? SH1 : SH0);
            #pragma unroll
            for (int ks = 0; ks < 2; ks++) {
                uint32_t bh[2][4];
                #pragma unroll
                for (int np = 0; np < 2; np++) {
                    int p = pb + np*16 + (lane & 7) + ((lane >> 4) << 3);
                    int u = ks*2 + ((lane >> 3) & 1);
                    uint32_t bd = shb + (uint32_t)p*64u + (uint32_t)((u ^ ((p>>1)&3)) << 4);
                    ldsm4(bh[np], bd);
                }
                #pragma unroll
                for (int mt = 0; mt < 4; mt++) {
                    int o = ob + mt*16 + (lane & 15);
                    int u = ks*2 + (lane >> 4);
                    uint32_t ad = whb + (uint32_t)o*64u + (uint32_t)((u ^ ((o>>1)&3)) << 4);
                    uint32_t ah[4];
                    ldsm4(ah, ad);
                    #pragma unroll
                    for (int np = 0; np < 2; np++)
                        #pragma unroll
                        for (int hf = 0; hf < 2; hf++)
                            mma_h(acc[mt][np*2+hf], ah, bh[np][hf*2], bh[np][hf*2+1]);
                }
            }
        }

        // ---- finish gather: half2 interp + STS for s chunk q+1 ----
        if (more) {
            uint32_t sdst = ((q+1) & 1) ? SH1 : SH0;
            uint4 r = interp_h2(C0, C1, C2, C3, w00, w01, w10, w11, mmv);
            *(uint4*)(smc + sdst + s_off) = r;
        }

        __syncthreads();
    }

    // ---- epilogue: BN + ReLU ----
    int tg = lane & 3, g = lane >> 2;
    #pragma unroll
    for (int mt = 0; mt < 4; mt++) {
        int o0 = ob + mt*16 + g;
        int o1 = o0 + 8;
        float A0 = g_bnA[o0], B0 = g_bnB[o0];
        float A1 = g_bnA[o1], B1 = g_bnB[o1];
        float* r0 = out + ((size_t)(b*On + o0))*HWn + hwb;
        float* r1 = out + ((size_t)(b*On + o1))*HWn + hwb;
        #pragma unroll
        for (int nt = 0; nt < 4; nt++) {
            int p0 = pb + nt*8 + tg*2;
            float2 v0, v1;
            v0.x = fmaxf(acc[mt][nt][0]*A0 + B0, 0.f);
            v0.y = fmaxf(acc[mt][nt][1]*A0 + B0, 0.f);
            v1.x = fmaxf(acc[mt][nt][2]*A1 + B1, 0.f);
            v1.y = fmaxf(acc[mt][nt][3]*A1 + B1, 0.f);
            *(float2*)(r0 + p0) = v0;
            *(float2*)(r1 + p0) = v1;
        }
    }
}

// ---------------- launch ----------------
extern "C" void kernel_launch(void* const* d_in, const int* in_sizes, int n_in,
                              void* d_out, int out_size) {
    const float* x      = (const float*)d_in[0];
    const float* w_off  = (const float*)d_in[1];
    const float* b_off  = (const float*)d_in[2];
    const float* w_dcn  = (const float*)d_in[3];
    const float* b_dcn  = (const float*)d_in[4];
    const float* gamma  = (const float*)d_in[5];
    const float* beta   = (const float*)d_in[6];
    const float* rmean  = (const float*)d_in[7];
    const float* rvar   = (const float*)d_in[8];
    float* out = (float*)d_out;

    cudaFuncSetAttribute(main_kernel, cudaFuncAttributeMaxDynamicSharedMemorySize, SMEM_BYTES);
    cudaFuncSetAttribute(main_kernel, cudaFuncAttributePreferredSharedMemoryCarveout, 100);
    cudaFuncSetAttribute(offset_mma_kernel, cudaFuncAttributeMaxDynamicSharedMemorySize, OSMEM);

    prep_kernel<<<256, 256>>>(w_off, w_dcn, b_dcn, gamma, beta, rmean, rvar);

    dim3 tgrid(Wn/32, Cn/32, Bn*Hn);
    transpose_kernel<<<tgrid, dim3(32, 8)>>>(x);

    offset_mma_kernel<<<(Bn*HWn)/OTP, ONT, OSMEM>>>(b_off);

    main_kernel<<<(Bn*HWn)/TPIX, NT, SMEM_BYTES>>>(out);
}

// round 15
// speedup vs baseline: 6.3170x; 1.0773x over previous
#include <cuda_runtime.h>
#include <cuda_fp16.h>
#include <cstdint>

typedef unsigned long long ull;

#define KKn  9
#define Bn   8
#define Cn   256
#define Hn   96
#define Wn   96
#define On   256
#define HWn  (Hn*Wn)          // 9216
#define KDIM (Cn*KKn)         // 2304

// ---- main mma kernel ----
#define NT    256
#define TPIX  64              // pixels per CTA
#define NCH   72              // K chunks of 32
#define NCOORD (TPIX*KKn)     // 576

// main smem byte offsets (fp16 1-pass: w hi; s hi only)
#define WH0   0u              // [256][32] fp16 = 16384
#define WH1   16384u
#define SH0   32768u          // [64][32] fp16 = 4096
#define SH1   36864u
#define CO_B  40960u
#define SMEM_BYTES (40960 + 3*NCOORD*4)   // 47872 -> 2 blocks/SM

// ---- offset mma kernel (1-pass fp16) ----
#define ONT   128
#define OTP   128             // pixels per CTA
#define OAH0  0u              // [32][32] fp16 = 2048
#define OAH1  2048u
#define OBH0  4096u           // [128][32] fp16 = 8192
#define OBH1  12288u
#define OV_B  20480u
#define OVSTR 132
#define OSMEM (20480 + 28*OVSTR*4)        // 35264

// ---------------- scratch ----------------
__device__ __half g_xth[Bn*HWn*Cn];      // x transposed to NHWC, fp16
__device__ float g_py [Bn*KKn*HWn];
__device__ float g_px [Bn*KKn*HWn];
__device__ float g_msk[Bn*KKn*HWn];
__device__ __half g_wh [On*KDIM];        // main w fp16 [o][kk*256+c]
__device__ __half g_woh[32*KDIM];        // offset w fp16 [o pad32][kk*256+c]
__device__ float g_bnA[On];
__device__ float g_bnB[On];

// ---------------- helpers ----------------
__device__ __forceinline__ uint32_t smem_u32(const void* p) {
    return (uint32_t)__cvta_generic_to_shared(p);
}
__device__ __forceinline__ void cp16(uint32_t dst, const void* src) {
    asm volatile("cp.async.cg.shared.global [%0], [%1], 16;" :: "r"(dst), "l"(src));
}
__device__ __forceinline__ void cp16z(uint32_t dst, const void* src, uint32_t sz) {
    asm volatile("cp.async.cg.shared.global [%0], [%1], 16, %2;"
        :: "r"(dst), "l"(src), "r"(sz));
}
#define CP_COMMIT()  asm volatile("cp.async.commit_group;")
#define CP_WAIT0()   asm volatile("cp.async.wait_group 0;")

__device__ __forceinline__ void ldsm4(uint32_t* r, uint32_t addr) {
    asm volatile("ldmatrix.sync.aligned.m8n8.x4.shared.b16 {%0,%1,%2,%3}, [%4];"
        : "=r"(r[0]), "=r"(r[1]), "=r"(r[2]), "=r"(r[3]) : "r"(addr));
}
__device__ __forceinline__ void mma_h(float* d, const uint32_t* a, uint32_t b0, uint32_t b1) {
    asm volatile("mma.sync.aligned.m16n8k16.row.col.f32.f16.f16.f32 "
        "{%0,%1,%2,%3}, {%4,%5,%6,%7}, {%8,%9}, {%0,%1,%2,%3};"
        : "+f"(d[0]), "+f"(d[1]), "+f"(d[2]), "+f"(d[3])
        : "r"(a[0]), "r"(a[1]), "r"(a[2]), "r"(a[3]), "r"(b0), "r"(b1));
}

// ---------------- prep ----------------
__global__ void prep_kernel(const float* __restrict__ w_off,
                            const float* __restrict__ w_dcn,
                            const float* __restrict__ b_dcn,
                            const float* __restrict__ gamma,
                            const float* __restrict__ beta,
                            const float* __restrict__ rmean,
                            const float* __restrict__ rvar) {
    int t = blockIdx.x * blockDim.x + threadIdx.x;
    int stride = gridDim.x * blockDim.x;
    for (int i = t; i < On*KDIM; i += stride) {
        int K = i % KDIM; int o = i / KDIM;
        int kk = K / Cn;  int c = K % Cn;
        g_wh[i] = __float2half_rn(w_dcn[(o*Cn + c)*KKn + kk]);
    }
    for (int i = t; i < 32*KDIM; i += stride) {
        int K = i % KDIM; int o = i / KDIM;
        int kk = K / Cn;  int c = K % Cn;
        float v = (o < 27) ? w_off[(o*Cn + c)*KKn + kk] : 0.f;
        g_woh[i] = __float2half_rn(v);
    }
    if (t < On) {
        float inv = rsqrtf(rvar[t] + 1e-5f);
        float A = gamma[t] * inv;
        g_bnA[t] = A;
        g_bnB[t] = (b_dcn[t] - rmean[t]) * A + beta[t];
    }
}

// ---------------- NCHW fp32 -> NHWC fp16 transpose ----------------
__global__ void transpose_kernel(const float* __restrict__ x) {
    __shared__ float tile[32][33];
    int bh = blockIdx.z;
    int c0 = blockIdx.y * 32;
    int w0 = blockIdx.x * 32;
    int b = bh / Hn; int h = bh % Hn;
    for (int i = threadIdx.y; i < 32; i += 8)
        tile[i][threadIdx.x] = x[((b*Cn + c0 + i)*Hn + h)*Wn + w0 + threadIdx.x];
    __syncthreads();
    for (int i = threadIdx.y; i < 32; i += 8)
        g_xth[((size_t)(b*Hn + h)*Wn + w0 + i)*Cn + c0 + threadIdx.x] =
            __float2half_rn(tile[threadIdx.x][i]);
}

// ---------------- offset conv via fp16 1-pass mma ----------------
__global__ __launch_bounds__(ONT) void offset_mma_kernel(const float* __restrict__ b_off) {
    extern __shared__ char smc[];
    uint32_t sb = smem_u32(smc);
    float* ov = (float*)(smc + OV_B);

    int tid  = threadIdx.x;
    int lane = tid & 31;
    int wid  = tid >> 5;
    int pixb = blockIdx.x * OTP;
    int b    = pixb / HWn;
    int hwb  = pixb % HWn;
    const __half* xtbh = g_xth + (size_t)b * (HWn*Cn);

    // stage chunk q: A weights + B tile, all via cp.async (zfill for OOB)
    auto stage = [&](int q) {
        uint32_t ab = (q & 1) ? OAH1 : OAH0;
        uint32_t bb = (q & 1) ? OBH1 : OBH0;
        {
            int row = tid >> 2, quad = tid & 3;
            cp16(sb + ab + (uint32_t)row*64u + (uint32_t)((quad ^ ((row>>1)&3)) << 4),
                 g_woh + (size_t)row*KDIM + q*32 + quad*8);
        }
        int kk = q >> 3;
        int c32 = (q & 7) * 32;
        int dy = kk/3 - 1, dx = kk%3 - 1;
        #pragma unroll
        for (int i = 0; i < 4; i++) {
            int t = i*ONT + tid;
            int p = t >> 2, quad = t & 3;
            int hw = hwb + p;
            int h = hw / Wn, w = hw % Wn;
            int y = h + dy, x = w + dx;
            bool ok = ((unsigned)y < (unsigned)Hn) && ((unsigned)x < (unsigned)Wn);
            const __half* src = ok ? (xtbh + (((y*Wn + x) << 8) + c32 + quad*8)) : xtbh;
            uint32_t dst = sb + bb + (uint32_t)p*64u + (uint32_t)((quad ^ ((p>>1)&3)) << 4);
            cp16z(dst, src, ok ? 16u : 0u);
        }
        CP_COMMIT();
    };

    stage(0);

    int pb = wid * 32;
    float acc[2][4][4];
    #pragma unroll
    for (int mt = 0; mt < 2; mt++)
        #pragma unroll
        for (int nt = 0; nt < 4; nt++)
            #pragma unroll
            for (int e = 0; e < 4; e++) acc[mt][nt][e] = 0.f;

    #pragma unroll 1
    for (int q = 0; q < NCH; q++) {
        int buf = q & 1;
        bool more = (q + 1 < NCH);
        CP_WAIT0();        // chunk q arrived (only group outstanding)
        __syncthreads();   // visible to all; all warps done reading buffer (q-1)&1

        if (more) stage(q+1);   // post-barrier: target buffer provably free

        uint32_t ab = sb + (buf ? OAH1 : OAH0);
        uint32_t bb = sb + (buf ? OBH1 : OBH0);
        #pragma unroll
        for (int ks = 0; ks < 2; ks++) {
            uint32_t bh[2][4];
            #pragma unroll
            for (int np = 0; np < 2; np++) {
                int p = pb + np*16 + (lane & 7) + ((lane >> 4) << 3);
                int u = ks*2 + ((lane >> 3) & 1);
                uint32_t bd = bb + (uint32_t)p*64u + (uint32_t)((u ^ ((p>>1)&3)) << 4);
                ldsm4(bh[np], bd);
            }
            #pragma unroll
            for (int mt = 0; mt < 2; mt++) {
                int o = mt*16 + (lane & 15);
                int u = ks*2 + (lane >> 4);
                uint32_t ad = ab + (uint32_t)o*64u + (uint32_t)((u ^ ((o>>1)&3)) << 4);
                uint32_t ah[4];
                ldsm4(ah, ad);
                #pragma unroll
                for (int np = 0; np < 2; np++)
                    #pragma unroll
                    for (int hf = 0; hf < 2; hf++)
                        mma_h(acc[mt][np*2+hf], ah, bh[np][hf*2], bh[np][hf*2+1]);
            }
        }
    }
    __syncthreads();

    // ---- write acc to ov ----
    #pragma unroll
    for (int mt = 0; mt < 2; mt++) {
        int o0 = mt*16 + (lane >> 2);
        int o1 = o0 + 8;
        #pragma unroll
        for (int nt = 0; nt < 4; nt++) {
            int p = pb + nt*8 + (lane & 3)*2;
            if (o0 < 27) {
                ov[o0*OVSTR + p]   = acc[mt][nt][0];
                ov[o0*OVSTR + p+1] = acc[mt][nt][1];
            }
            if (o1 < 27) {
                ov[o1*OVSTR + p]   = acc[mt][nt][2];
                ov[o1*OVSTR + p+1] = acc[mt][nt][3];
            }
        }
    }
    __syncthreads();

    // ---- epilogue: py/px/mask ----
    {
        int p = tid;
        int hw = hwb + p;
        int h = hw / Wn, w = hw % Wn;
        #pragma unroll
        for (int k = 0; k < KKn; k++) {
            float py = ov[(2*k)*OVSTR + p]   + b_off[2*k]   + (float)(h + k/3 - 1);
            float px = ov[(2*k+1)*OVSTR + p] + b_off[2*k+1] + (float)(w + k%3 - 1);
            float mv = ov[(18+k)*OVSTR + p]  + b_off[18+k];
            float mm = 1.f / (1.f + expf(-mv));
            int idx = (b*KKn + k)*HWn + hw;
            g_py[idx] = py; g_px[idx] = px; g_msk[idx] = mm;
        }
    }
}

// ---------------- main: fp16 1-pass mma fused DCN (fp16 gather) ----------------
__device__ __forceinline__ uint4 corner_ldh(const __half* __restrict__ xtbh, int y, int x, int c) {
    if ((unsigned)y < (unsigned)Hn && (unsigned)x < (unsigned)Wn)
        return *(const uint4*)(xtbh + (((y*Wn + x) << 8) + c));
    return make_uint4(0u, 0u, 0u, 0u);
}

__global__ __launch_bounds__(NT, 2) void main_kernel(float* __restrict__ out) {
    extern __shared__ char smc[];
    uint32_t sb = smem_u32(smc);
    float* spy = (float*)(smc + CO_B);
    float* spx = spy + NCOORD;
    float* smk = spx + NCOORD;

    int tid  = threadIdx.x;
    int lane = tid & 31;
    int wid  = tid >> 5;
    int pixb = blockIdx.x * TPIX;
    int b    = pixb / HWn;
    int hwb  = pixb % HWn;

    for (int i = tid; i < NCOORD; i += NT) {
        int p = i / KKn, k = i % KKn;
        int gi = (b*KKn + k)*HWn + hwb + p;
        spy[i] = g_py[gi]; spx[i] = g_px[gi]; smk[i] = g_msk[gi];
    }
    __syncthreads();

    const __half* xtbh = g_xth + (size_t)b * (HWn*Cn);

    int gp  = tid >> 2;        // pixel 0..63
    int gcq = tid & 3;         // 8-channel (16B) group
    uint32_t s_off = (uint32_t)gp*64u + (uint32_t)((gcq ^ ((gp >> 1) & 3)) << 4);

    auto cpW = [&](int q) {
        uint32_t wb = (q & 1) ? WH1 : WH0;
        #pragma unroll
        for (int i = 0; i < 4; i++) {
            int id = i*NT + tid;
            int o = id >> 2;
            int u = id & 3;
            const __half* src = g_wh + (size_t)o*KDIM + q*32 + u*8;
            uint32_t dst = sb + wb + (uint32_t)o*64u
                         + (uint32_t)((u ^ ((o>>1)&3)) << 4);
            cp16(dst, src);
        }
        CP_COMMIT();
    };

    // ---- per-slice gather state (hoisted: refreshed once per 8 chunks) ----
    int y0s, x0s;
    __half2 W00, W01, W10, W11, MMh;
    auto refresh = [&](int kk) {
        float py = spy[gp*KKn + kk], px = spx[gp*KKn + kk], mm = smk[gp*KKn + kk];
        float fy = floorf(py), fx = floorf(px);
        y0s = (int)fy; x0s = (int)fx;
        float wy = py - fy, wx = px - fx;
        W00 = __float2half2_rn((1.f-wy)*(1.f-wx));
        W01 = __float2half2_rn((1.f-wy)*wx);
        W10 = __float2half2_rn(wy*(1.f-wx));
        W11 = __float2half2_rn(wy*wx);
        MMh = __float2half2_rn(mm);
    };
    auto interp_h2 = [&](uint4 C0, uint4 C1, uint4 C2, uint4 C3) -> uint4 {
        const __half2* c0 = (const __half2*)&C0;
        const __half2* c1 = (const __half2*)&C1;
        const __half2* c2 = (const __half2*)&C2;
        const __half2* c3 = (const __half2*)&C3;
        uint4 res;
        __half2* rp = (__half2*)&res;
        #pragma unroll
        for (int j = 0; j < 4; j++) {
            __half2 a = __hmul2(c0[j], W00);
            a = __hfma2(c1[j], W01, a);
            a = __hfma2(c2[j], W10, a);
            a = __hfma2(c3[j], W11, a);
            rp[j] = __hmul2(a, MMh);
        }
        return res;
    };

    // prologue: w chunk 0 + s chunk 0
    {
        cpW(0);
        refresh(0);
        int c = gcq*8;
        uint4 C0 = corner_ldh(xtbh, y0s,   x0s,   c);
        uint4 C1 = corner_ldh(xtbh, y0s,   x0s+1, c);
        uint4 C2 = corner_ldh(xtbh, y0s+1, x0s,   c);
        uint4 C3 = corner_ldh(xtbh, y0s+1, x0s+1, c);
        uint4 r = interp_h2(C0, C1, C2, C3);
        *(uint4*)(smc + SH0 + s_off) = r;
    }

    int ob = (wid >> 1) * 64;
    int pb = (wid & 1) * 32;
    float acc[4][4][4];
    #pragma unroll
    for (int mt = 0; mt < 4; mt++)
        #pragma unroll
        for (int nt = 0; nt < 4; nt++)
            #pragma unroll
            for (int e = 0; e < 4; e++) acc[mt][nt][e] = 0.f;

    #pragma unroll 1
    for (int q = 0; q < NCH; q++) {
        int buf = q & 1;
        bool more = (q + 1 < NCH);

        // ---- pre-issue corner LDGs for s chunk q+1 (state hoisted per slice) ----
        uint4 C0, C1, C2, C3;
        if (more) {
            int qn = q + 1;
            if ((qn & 7) == 0) refresh(qn >> 3);
            int c = ((qn & 7) << 5) + gcq*8;
            C0 = corner_ldh(xtbh, y0s,   x0s,   c);
            C1 = corner_ldh(xtbh, y0s,   x0s+1, c);
            C2 = corner_ldh(xtbh, y0s+1, x0s,   c);
            C3 = corner_ldh(xtbh, y0s+1, x0s+1, c);
        }

        CP_WAIT0();        // this thread's cp for chunk q complete
        __syncthreads();   // chunk q visible; all warps done reading buffer (q-1)&1

        if (more) cpW(q+1);   // post-barrier: w buffer (q+1)&1 provably free

        // ---- MMA on chunk q ----
        {
            uint32_t whb = sb + (buf ? WH1 : WH0);
            uint32_t shb = sb + (buf ? SH1 : SH0);
            #pragma unroll
            for (int ks = 0; ks < 2; ks++) {
                uint32_t bh[2][4];
                #pragma unroll
                for (int np = 0; np < 2; np++) {
                    int p = pb + np*16 + (lane & 7) + ((lane >> 4) << 3);
                    int u = ks*2 + ((lane >> 3) & 1);
                    uint32_t bd = shb + (uint32_t)p*64u + (uint32_t)((u ^ ((p>>1)&3)) << 4);
                    ldsm4(bh[np], bd);
                }
                #pragma unroll
                for (int mt = 0; mt < 4; mt++) {
                    int o = ob + mt*16 + (lane & 15);
                    int u = ks*2 + (lane >> 4);
                    uint32_t ad = whb + (uint32_t)o*64u + (uint32_t)((u ^ ((o>>1)&3)) << 4);
                    uint32_t ah[4];
                    ldsm4(ah, ad);
                    #pragma unroll
                    for (int np = 0; np < 2; np++)
                        #pragma unroll
                        for (int hf = 0; hf < 2; hf++)
                            mma_h(acc[mt][np*2+hf], ah, bh[np][hf*2], bh[np][hf*2+1]);
                }
            }
        }

        // ---- finish gather: half2 interp + STS for s chunk q+1 ----
        // (s buffer (q+1)&1 was last read in iteration q-1; all warps passed
        //  this iteration's barrier, so the write is safe; readers of chunk q+1
        //  sync at the next iteration's barrier.)
        if (more) {
            uint32_t sdst = ((q+1) & 1) ? SH1 : SH0;
            uint4 r = interp_h2(C0, C1, C2, C3);
            *(uint4*)(smc + sdst + s_off) = r;
        }
    }

    // ---- epilogue: BN + ReLU ----
    int tg = lane & 3, g = lane >> 2;
    #pragma unroll
    for (int mt = 0; mt < 4; mt++) {
        int o0 = ob + mt*16 + g;
        int o1 = o0 + 8;
        float A0 = g_bnA[o0], B0 = g_bnB[o0];
        float A1 = g_bnA[o1], B1 = g_bnB[o1];
        float* r0 = out + ((size_t)(b*On + o0))*HWn + hwb;
        float* r1 = out + ((size_t)(b*On + o1))*HWn + hwb;
        #pragma unroll
        for (int nt = 0; nt < 4; nt++) {
            int p0 = pb + nt*8 + tg*2;
            float2 v0, v1;
            v0.x = fmaxf(acc[mt][nt][0]*A0 + B0, 0.f);
            v0.y = fmaxf(acc[mt][nt][1]*A0 + B0, 0.f);
            v1.x = fmaxf(acc[mt][nt][2]*A1 + B1, 0.f);
            v1.y = fmaxf(acc[mt][nt][3]*A1 + B1, 0.f);
            *(float2*)(r0 + p0) = v0;
            *(float2*)(r1 + p0) = v1;
        }
    }
}

// ---------------- launch ----------------
extern "C" void kernel_launch(void* const* d_in, const int* in_sizes, int n_in,
                              void* d_out, int out_size) {
    const float* x      = (const float*)d_in[0];
    const float* w_off  = (const float*)d_in[1];
    const float* b_off  = (const float*)d_in[2];
    const float* w_dcn  = (const float*)d_in[3];
    const float* b_dcn  = (const float*)d_in[4];
    const float* gamma  = (const float*)d_in[5];
    const float* beta   = (const float*)d_in[6];
    const float* rmean  = (const float*)d_in[7];
    const float* rvar   = (const float*)d_in[8];
    float* out = (float*)d_out;

    cudaFuncSetAttribute(main_kernel, cudaFuncAttributeMaxDynamicSharedMemorySize, SMEM_BYTES);
    cudaFuncSetAttribute(main_kernel, cudaFuncAttributePreferredSharedMemoryCarveout, 100);
    cudaFuncSetAttribute(offset_mma_kernel, cudaFuncAttributeMaxDynamicSharedMemorySize, OSMEM);

    prep_kernel<<<256, 256>>>(w_off, w_dcn, b_dcn, gamma, beta, rmean, rvar);

    dim3 tgrid(Wn/32, Cn/32, Bn*Hn);
    transpose_kernel<<<tgrid, dim3(32, 8)>>>(x);

    offset_mma_kernel<<<(Bn*HWn)/OTP, ONT, OSMEM>>>(b_off);

    main_kernel<<<(Bn*HWn)/TPIX, NT, SMEM_BYTES>>>(out);
}